// round 14
// baseline (speedup 1.0000x reference)
#include <cuda_runtime.h>
#include <cuda_bf16.h>
#include <cuda_fp16.h>
#include <math.h>
#include <stdint.h>

// Problem dims (fixed for this dataset)
constexpr int S_  = 256;
constexpr int B_  = 8;
constexpr int T_  = 1024;
constexpr int D_  = 512;
constexpr int TS_ = 512;
constexpr int V_  = 32000;
constexpr int SB  = S_ * B_;   // 2048
constexpr int TB  = T_ * B_;   // 8192

// ---------------------------------------------------------------------------
// Scratch arena
// ---------------------------------------------------------------------------
constexpr size_t OQ  = 0;                        // q / later x      : SB*D
constexpr size_t OK_ = OQ  + (size_t)SB * D_;    // k                : TB*D
constexpr size_t OV  = OK_ + (size_t)TB * D_;    // v                : TB*D
constexpr size_t OVT = OV  + (size_t)TB * D_;    // v transposed     : TB*D
constexpr size_t OA  = OVT + (size_t)TB * D_;    // attn (scores)    : SB*T
constexpr size_t OC  = OA  + (size_t)SB * T_;    // ctx              : SB*D
constexpr size_t OL  = OC  + (size_t)SB * D_;    // layernorm out    : SB*D
constexpr size_t OT  = OL  + (size_t)SB * D_;    // outs_token (f32) : SB*D
constexpr size_t OG  = OT  + (size_t)SB * D_;    // gates            : SB*2
constexpr size_t ORS = OG  + (size_t)SB * 2;     // rowsum exp       : SB
constexpr size_t OWB = ORS + SB;                 // Wgen f16         : V*TS/2 floats
constexpr size_t OTB = OWB + (size_t)V_ * TS_ / 2;  // tok f16       : SB*TS/2
constexpr size_t SCRATCH_FLOATS = OTB + (size_t)SB * TS_ / 2;

__device__ float g_scratch[SCRATCH_FLOATS];

// ---------------------------------------------------------------------------
// math helpers
// ---------------------------------------------------------------------------
__device__ __forceinline__ float fexp(float x) {
    float t = fmaxf(fminf(x * 1.4426950408889634f, 126.f), -126.f);
    float mg = t + 12582912.f;
    int   n  = __float_as_int(mg) - 0x4B400000;
    float f  = t - (mg - 12582912.f);
    float p  = 1.54035304e-4f;
    p = fmaf(p, f, 1.33335581e-3f);
    p = fmaf(p, f, 9.61812911e-3f);
    p = fmaf(p, f, 5.55041087e-2f);
    p = fmaf(p, f, 2.40226507e-1f);
    p = fmaf(p, f, 6.93147182e-1f);
    p = fmaf(p, f, 1.0f);
    return __int_as_float(__float_as_int(p) + (n << 23));
}

__device__ __forceinline__ void mma_tf32(float& c0, float& c1, float& c2, float& c3,
                                         unsigned a0, unsigned a1, unsigned a2, unsigned a3,
                                         unsigned b0, unsigned b1)
{
    asm volatile(
        "mma.sync.aligned.m16n8k8.row.col.f32.tf32.tf32.f32 "
        "{%0,%1,%2,%3}, {%4,%5,%6,%7}, {%8,%9}, {%0,%1,%2,%3};"
        : "+f"(c0), "+f"(c1), "+f"(c2), "+f"(c3)
        : "r"(a0), "r"(a1), "r"(a2), "r"(a3), "r"(b0), "r"(b1));
}

// f16 in, f16 accumulate (tests the half-rate-f32-accum hypothesis)
__device__ __forceinline__ void mma_f16(unsigned& c0, unsigned& c1,
                                        unsigned a0, unsigned a1, unsigned a2, unsigned a3,
                                        unsigned b0, unsigned b1)
{
    asm volatile(
        "mma.sync.aligned.m16n8k16.row.col.f16.f16.f16.f16 "
        "{%0,%1}, {%2,%3,%4,%5}, {%6,%7}, {%0,%1};"
        : "+r"(c0), "+r"(c1)
        : "r"(a0), "r"(a1), "r"(a2), "r"(a3), "r"(b0), "r"(b1));
}

__device__ __forceinline__ void ldsm_x4(unsigned& r0, unsigned& r1, unsigned& r2, unsigned& r3,
                                        unsigned addr)
{
    asm volatile("ldmatrix.sync.aligned.m8n8.x4.shared.b16 {%0,%1,%2,%3}, [%4];"
                 : "=r"(r0), "=r"(r1), "=r"(r2), "=r"(r3) : "r"(addr));
}

__device__ __forceinline__ void cp16(unsigned dst, const void* src) {
    asm volatile("cp.async.cg.shared.global [%0], [%1], 16;\n" :: "r"(dst), "l"(src));
}

// ---------------------------------------------------------------------------
// Tensor-core NT GEMM (tf32): C[m,n] = ACT(alpha*(sum A[m,k]*B[n,k] + bias[n]))
// 128x128 block, 4 warps, warp tile 64x64, BK=32, 64KB SMEM, 2 CTAs/SM.
// If ACT==1 and Ch, also emits f16 copy of C.
// ---------------------------------------------------------------------------
template <int ACT>
__global__ __launch_bounds__(128, 2)
void mma_nt_kernel(const float* __restrict__ A, const float* __restrict__ Bm,
                   const float* __restrict__ bias, float* __restrict__ C,
                   __half* __restrict__ Ch,
                   int K, int lda, int ldb, int ldc,
                   long sA, long sB, long sC, float alpha)
{
    extern __shared__ unsigned sh[];

    A  += (long)blockIdx.z * sA;
    Bm += (long)blockIdx.z * sB;
    C  += (long)blockIdx.z * sC;

    const int t    = threadIdx.x;
    const int lane = t & 31;
    const int warp = t >> 5;
    const int wm   = (warp >> 1) * 64;
    const int wn   = (warp & 1) * 64;
    const int grp  = lane >> 2;
    const int qid  = lane & 3;

    const long m0 = (long)blockIdx.y * 128;
    const long n0 = (long)blockIdx.x * 128;

    float acc[4][8][4];
#pragma unroll
    for (int mi = 0; mi < 4; mi++)
#pragma unroll
        for (int ni = 0; ni < 8; ni++)
#pragma unroll
            for (int c = 0; c < 4; c++) acc[mi][ni][c] = 0.f;

    const int row0 = t >> 3;
    const int c4   = t & 7;
    const float* aptr0 = A  + (m0 + row0) * lda + c4 * 4;
    const float* bptr0 = Bm + (n0 + row0) * ldb + c4 * 4;
    const unsigned soff0 = (unsigned)(row0 * 32 + ((c4 ^ (row0 & 7)) << 2)) * 4u;
    const unsigned sbase = (unsigned)__cvta_generic_to_shared(sh);

    auto issue = [&](int stage, int koff) {
        unsigned ab = sbase + (unsigned)stage * 16384u + soff0;
        unsigned bb = sbase + 32768u + (unsigned)stage * 16384u + soff0;
#pragma unroll
        for (int i = 0; i < 8; i++) {
            cp16(ab + i * 2048u, aptr0 + (long)i * 16 * lda + koff);
            cp16(bb + i * 2048u, bptr0 + (long)i * 16 * ldb + koff);
        }
        asm volatile("cp.async.commit_group;\n" ::: "memory");
    };

    issue(0, 0);
    const int nIter = K >> 5;
    for (int it = 0; it < nIter; ++it) {
        asm volatile("cp.async.wait_group 0;\n" ::: "memory");
        __syncthreads();
        if (it + 1 < nIter) issue((it + 1) & 1, (it + 1) * 32);

        const unsigned* Asb = sh + (it & 1) * 4096;
        const unsigned* Bsb = sh + 8192 + (it & 1) * 4096;
#pragma unroll
        for (int kk = 0; kk < 4; kk++) {
            unsigned af[4][4], bf[8][2];
#pragma unroll
            for (int mi = 0; mi < 4; mi++) {
                int m  = wm + mi * 16 + grp;
                int m8 = m + 8;
                af[mi][0] = Asb[m  * 32 + ((( kk * 2    ) ^ (m  & 7)) << 2) + qid];
                af[mi][1] = Asb[m8 * 32 + ((( kk * 2    ) ^ (m8 & 7)) << 2) + qid];
                af[mi][2] = Asb[m  * 32 + ((( kk * 2 + 1) ^ (m  & 7)) << 2) + qid];
                af[mi][3] = Asb[m8 * 32 + ((( kk * 2 + 1) ^ (m8 & 7)) << 2) + qid];
            }
#pragma unroll
            for (int ni = 0; ni < 8; ni++) {
                int n = wn + ni * 8 + grp;
                bf[ni][0] = Bsb[n * 32 + ((( kk * 2    ) ^ (n & 7)) << 2) + qid];
                bf[ni][1] = Bsb[n * 32 + ((( kk * 2 + 1) ^ (n & 7)) << 2) + qid];
            }
#pragma unroll
            for (int mi = 0; mi < 4; mi++)
#pragma unroll
                for (int ni = 0; ni < 8; ni++)
                    mma_tf32(acc[mi][ni][0], acc[mi][ni][1], acc[mi][ni][2], acc[mi][ni][3],
                             af[mi][0], af[mi][1], af[mi][2], af[mi][3],
                             bf[ni][0], bf[ni][1]);
        }
    }

#pragma unroll
    for (int mi = 0; mi < 4; mi++) {
        long r0 = m0 + wm + mi * 16 + grp;
        long r1 = r0 + 8;
#pragma unroll
        for (int ni = 0; ni < 8; ni++) {
            long col = n0 + wn + ni * 8 + qid * 2;
            float bv0 = 0.f, bv1 = 0.f;
            if (bias) { bv0 = bias[col]; bv1 = bias[col + 1]; }
            float v00 = (acc[mi][ni][0] + bv0) * alpha;
            float v01 = (acc[mi][ni][1] + bv1) * alpha;
            float v10 = (acc[mi][ni][2] + bv0) * alpha;
            float v11 = (acc[mi][ni][3] + bv1) * alpha;
            if (ACT == 1) { v00 = tanhf(v00); v01 = tanhf(v01); v10 = tanhf(v10); v11 = tanhf(v11); }
            *(float2*)(C + r0 * ldc + col) = make_float2(v00, v01);
            *(float2*)(C + r1 * ldc + col) = make_float2(v10, v11);
            if (ACT == 1 && Ch) {
                *(__half2*)(Ch + r0 * ldc + col) = __floats2half2_rn(v00, v01);
                *(__half2*)(Ch + r1 * ldc + col) = __floats2half2_rn(v10, v11);
            }
        }
    }
}

// ---------------------------------------------------------------------------
// f16 NT GEMM + fused exp-rowsum: 128x128 block, 4 warps, warp 64x64, BK=64.
// f16 accumulate within each BK=64 chunk (4 mma steps), promoted to f32 per
// chunk. 2-stage cp.async (64KB SMEM), ldmatrix.x4, 2 CTAs/SM.
// ---------------------------------------------------------------------------
__global__ __launch_bounds__(128, 2)
void mma_f16_nt_kernel(const __half* __restrict__ A,
                       const __half* __restrict__ Bm,
                       const float* __restrict__ bias, float* __restrict__ C,
                       float* __restrict__ rowsum,
                       int K, int lda, int ldb, int ldc)
{
    extern __shared__ unsigned sh[];

    const int t    = threadIdx.x;
    const int lane = t & 31;
    const int warp = t >> 5;
    const int wm   = (warp >> 1) * 64;
    const int wn   = (warp & 1) * 64;
    const int grp  = lane >> 2;
    const int qid  = lane & 3;

    const long m0 = (long)blockIdx.y * 128;
    const long n0 = (long)blockIdx.x * 128;

    float acc[4][8][4];
#pragma unroll
    for (int mi = 0; mi < 4; mi++)
#pragma unroll
        for (int ni = 0; ni < 8; ni++)
#pragma unroll
            for (int c = 0; c < 4; c++) acc[mi][ni][c] = 0.f;

    const int row0 = t >> 3;
    const int c8   = t & 7;
    const __half* aptr0 = A  + (m0 + row0) * lda + c8 * 8;
    const __half* bptr0 = Bm + (n0 + row0) * ldb + c8 * 8;
    const unsigned soff0 = (unsigned)(row0 * 128 + ((c8 ^ (row0 & 7)) << 4));
    const unsigned sbase = (unsigned)__cvta_generic_to_shared(sh);

    const int a_lr = lane & 15;
    const int a_cs = lane >> 4;
    unsigned a_off[4]; int a_m7[4];
#pragma unroll
    for (int mi = 0; mi < 4; mi++) {
        int m = wm + mi * 16 + a_lr;
        a_off[mi] = (unsigned)(m * 128);
        a_m7[mi]  = m & 7;
    }
    const int b_g  = lane >> 3;
    const int b_cs = b_g & 1;
    unsigned b_off[4]; int b_n7[4];
#pragma unroll
    for (int p = 0; p < 4; p++) {
        int n = wn + p * 16 + ((b_g & 2) << 2) + (lane & 7);
        b_off[p] = (unsigned)(n * 128);
        b_n7[p]  = n & 7;
    }

    auto issue = [&](int stage, int koff) {
        unsigned ab = sbase + (unsigned)stage * 32768u + soff0;
        unsigned bb = ab + 16384u;
#pragma unroll
        for (int i = 0; i < 8; i++) {
            cp16(ab + i * 2048u, aptr0 + (long)i * 16 * lda + koff);
            cp16(bb + i * 2048u, bptr0 + (long)i * 16 * ldb + koff);
        }
        asm volatile("cp.async.commit_group;\n" ::: "memory");
    };

    const int nIter = K >> 6;                 // BK=64 (8 for K=512)
    issue(0, 0);
    for (int it = 0; it < nIter; ++it) {
        asm volatile("cp.async.wait_group 0;\n" ::: "memory");
        __syncthreads();
        if (it + 1 < nIter) issue((it + 1) & 1, (it + 1) * 64);

        unsigned abase = sbase + (unsigned)(it & 1) * 32768u;
        unsigned bbase = abase + 16384u;

        // f16 chunk accumulators (zeroed per chunk)
        unsigned acc_h[4][8][2];
#pragma unroll
        for (int mi = 0; mi < 4; mi++)
#pragma unroll
            for (int ni = 0; ni < 8; ni++) { acc_h[mi][ni][0] = 0u; acc_h[mi][ni][1] = 0u; }

#pragma unroll
        for (int kk = 0; kk < 4; kk++) {
            unsigned af[4][4], bf[8][2];
            int ca = kk * 2 + a_cs;
            int cb = kk * 2 + b_cs;
#pragma unroll
            for (int mi = 0; mi < 4; mi++) {
                unsigned addr = abase + a_off[mi] + (unsigned)((ca ^ a_m7[mi]) << 4);
                ldsm_x4(af[mi][0], af[mi][1], af[mi][2], af[mi][3], addr);
            }
#pragma unroll
            for (int p = 0; p < 4; p++) {
                unsigned addr = bbase + b_off[p] + (unsigned)((cb ^ b_n7[p]) << 4);
                ldsm_x4(bf[2*p][0], bf[2*p][1], bf[2*p+1][0], bf[2*p+1][1], addr);
            }
#pragma unroll
            for (int mi = 0; mi < 4; mi++)
#pragma unroll
                for (int ni = 0; ni < 8; ni++)
                    mma_f16(acc_h[mi][ni][0], acc_h[mi][ni][1],
                            af[mi][0], af[mi][1], af[mi][2], af[mi][3],
                            bf[ni][0], bf[ni][1]);
        }

        // promote chunk into f32 accumulators
#pragma unroll
        for (int mi = 0; mi < 4; mi++)
#pragma unroll
            for (int ni = 0; ni < 8; ni++) {
                float2 lo = __half22float2(*(__half2*)&acc_h[mi][ni][0]);
                float2 hi = __half22float2(*(__half2*)&acc_h[mi][ni][1]);
                acc[mi][ni][0] += lo.x; acc[mi][ni][1] += lo.y;
                acc[mi][ni][2] += hi.x; acc[mi][ni][3] += hi.y;
            }
    }

    // epilogue: write logits + per-row sum of exp
#pragma unroll
    for (int mi = 0; mi < 4; mi++) {
        long r0 = m0 + wm + mi * 16 + grp;
        long r1 = r0 + 8;
        float e0 = 0.f, e1 = 0.f;
#pragma unroll
        for (int ni = 0; ni < 8; ni++) {
            long col = n0 + wn + ni * 8 + qid * 2;
            float bv0 = bias[col], bv1 = bias[col + 1];
            float v00 = acc[mi][ni][0] + bv0;
            float v01 = acc[mi][ni][1] + bv1;
            float v10 = acc[mi][ni][2] + bv0;
            float v11 = acc[mi][ni][3] + bv1;
            *(float2*)(C + r0 * ldc + col) = make_float2(v00, v01);
            *(float2*)(C + r1 * ldc + col) = make_float2(v10, v11);
            e0 += fexp(v00) + fexp(v01);
            e1 += fexp(v10) + fexp(v11);
        }
        e0 += __shfl_xor_sync(0xFFFFFFFFu, e0, 1);
        e0 += __shfl_xor_sync(0xFFFFFFFFu, e0, 2);
        e1 += __shfl_xor_sync(0xFFFFFFFFu, e1, 1);
        e1 += __shfl_xor_sync(0xFFFFFFFFu, e1, 2);
        if (qid == 0) {
            atomicAdd(rowsum + r0, e0);
            atomicAdd(rowsum + r1, e1);
        }
    }
}

// ---------------------------------------------------------------------------
// fp32 -> f16 convert
// ---------------------------------------------------------------------------
__global__ __launch_bounds__(256)
void f2h_kernel(const float4* __restrict__ in, __half2* __restrict__ out, int n4)
{
    int i = blockIdx.x * 256 + threadIdx.x;
    if (i >= n4) return;
    float4 v = in[i];
    out[i * 2]     = __floats2half2_rn(v.x, v.y);
    out[i * 2 + 1] = __floats2half2_rn(v.z, v.w);
}

__global__ void zero_kernel(float* __restrict__ p)
{
    p[blockIdx.x * 256 + threadIdx.x] = 0.f;
}

// ---------------------------------------------------------------------------
// v transpose: vt[b][d][t] = v[(t*B+b)*D + d].
// ---------------------------------------------------------------------------
__global__ __launch_bounds__(256)
void vt_kernel(const float* __restrict__ v, float* __restrict__ vt)
{
    __shared__ float tile[32][33];
    int b  = blockIdx.z;
    int t0 = blockIdx.x * 32;
    int d0 = blockIdx.y * 32;
    int x  = threadIdx.x & 31;
    int y  = threadIdx.x >> 5;
#pragma unroll
    for (int j = 0; j < 32; j += 8)
        tile[y + j][x] = v[((long)(t0 + y + j) * B_ + b) * D_ + d0 + x];
    __syncthreads();
#pragma unroll
    for (int j = 0; j < 32; j += 8)
        vt[(long)b * D_ * T_ + (long)(d0 + y + j) * T_ + t0 + x] = tile[x][y + j];
}

// ---------------------------------------------------------------------------
// Softmax over T (in-place). mask: [B,T] bytes.
// ---------------------------------------------------------------------------
__global__ __launch_bounds__(256)
void attn_softmax_kernel(float* __restrict__ attn, const unsigned char* __restrict__ mask)
{
    int row = blockIdx.x;
    int b   = row & (B_ - 1);
    float* p = attn + (long)row * T_;
    const unsigned char* mrow = mask + (long)b * T_;
    int t = threadIdx.x;
    __shared__ float red[256];

    float x[4];
    float mx = -1e30f;
#pragma unroll
    for (int i = 0; i < 4; i++) {
        int tt = t + i * 256;
        float v = p[tt];
        if (mrow[tt]) v = -1e9f;
        x[i] = v;
        mx = fmaxf(mx, v);
    }
    red[t] = mx; __syncthreads();
    for (int s = 128; s > 0; s >>= 1) {
        if (t < s) red[t] = fmaxf(red[t], red[t + s]);
        __syncthreads();
    }
    mx = red[0]; __syncthreads();

    float sum = 0.f;
#pragma unroll
    for (int i = 0; i < 4; i++) { x[i] = fexp(x[i] - mx); sum += x[i]; }
    red[t] = sum; __syncthreads();
    for (int s = 128; s > 0; s >>= 1) {
        if (t < s) red[t] += red[t + s];
        __syncthreads();
    }
    float inv = 1.f / red[0];
#pragma unroll
    for (int i = 0; i < 4; i++) p[t + i * 256] = x[i] * inv;
}

// ---------------------------------------------------------------------------
// LayerNorm(outs + x).
// ---------------------------------------------------------------------------
__global__ __launch_bounds__(256)
void ln_kernel(const float* __restrict__ outs, const float* __restrict__ x,
               const float* __restrict__ g, const float* __restrict__ bb,
               float* __restrict__ out)
{
    int row = blockIdx.x;
    int t = threadIdx.x;
    const float* o  = outs + (long)row * D_;
    const float* xr = x    + (long)row * D_;
    __shared__ float red[256];

    float v0 = o[t] + xr[t];
    float v1 = o[t + 256] + xr[t + 256];

    red[t] = v0 + v1; __syncthreads();
    for (int s = 128; s > 0; s >>= 1) { if (t < s) red[t] += red[t + s]; __syncthreads(); }
    float mu = red[0] * (1.f / D_); __syncthreads();

    float d0 = v0 - mu, d1 = v1 - mu;
    red[t] = d0 * d0 + d1 * d1; __syncthreads();
    for (int s = 128; s > 0; s >>= 1) { if (t < s) red[t] += red[t + s]; __syncthreads(); }
    float inv = rsqrtf(red[0] * (1.f / D_) + 1e-5f);

    out[(long)row * D_ + t]       = d0 * inv * g[t]       + bb[t];
    out[(long)row * D_ + t + 256] = d1 * inv * g[t + 256] + bb[t + 256];
}

// ---------------------------------------------------------------------------
// 2-way gate
// ---------------------------------------------------------------------------
__global__ __launch_bounds__(128)
void gates_kernel(const float* __restrict__ tok, const float* __restrict__ Wdiv,
                  const float* __restrict__ bdiv, float* __restrict__ gates)
{
    int row = blockIdx.x;
    int t = threadIdx.x;
    const float* x = tok + (long)row * D_;
    float z0 = 0.f, z1 = 0.f;
    for (int d = t; d < D_; d += 128) {
        float xv = x[d];
        z0 = fmaf(xv, Wdiv[d],      z0);
        z1 = fmaf(xv, Wdiv[D_ + d], z1);
    }
    __shared__ float r0[128], r1[128];
    r0[t] = z0; r1[t] = z1; __syncthreads();
    for (int s = 64; s > 0; s >>= 1) {
        if (t < s) { r0[t] += r0[t + s]; r1[t] += r1[t + s]; }
        __syncthreads();
    }
    if (t == 0) {
        float a = r0[0] + bdiv[0], b = r1[0] + bdiv[1];
        float m = fmaxf(a, b);
        float e0 = __expf(a - m), e1 = __expf(b - m);
        float inv = 1.f / (e0 + e1);
        gates[row * 2 + 0] = e0 * inv;
        gates[row * 2 + 1] = e1 * inv;
    }
}

// ---------------------------------------------------------------------------
// Fused coef + log-prob base + copy-scatter. One block (256 thr) per row.
// ---------------------------------------------------------------------------
__global__ __launch_bounds__(256)
void lp_scatter_kernel(float* __restrict__ out, const float* __restrict__ rowsum,
                       const float* __restrict__ gates, const float* __restrict__ attn,
                       const int* __restrict__ copy_seq)
{
    int row = blockIdx.x;
    int t   = threadIdx.x;
    int b   = row & (B_ - 1);

    float coef = __logf(gates[row * 2 + 0]) - __logf(rowsum[row]);
    float gate1 = gates[row * 2 + 1];

    float4* o4 = (float4*)(out + (long)row * V_);
    for (int j = t; j < V_ / 4; j += 256) {
        float4 v = o4[j];
        v.x += coef; v.y += coef; v.z += coef; v.w += coef;
        o4[j] = v;
    }
    __syncthreads();

    const float* arow = attn + (long)row * T_;
    float* orow = out + (long)row * V_;
#pragma unroll
    for (int e = 0; e < 4; e++) {
        int tt = t + e * 256;
        float val = gate1 * arow[tt];
        int idx = copy_seq[tt * B_ + b];
        int* ia = (int*)(orow + idx);
        int assumed = *ia;
        int old;
        do {
            old = assumed;
            float cur = __int_as_float(old);
            float nv = __logf(__expf(cur) + val);
            assumed = atomicCAS(ia, old, __float_as_int(nv));
        } while (assumed != old);
    }
}

// ---------------------------------------------------------------------------
// Launch
// ---------------------------------------------------------------------------
extern "C" void kernel_launch(void* const* d_in, const int* in_sizes, int n_in,
                              void* d_out, int out_size)
{
    const float* outs = (const float*)d_in[0];
    const float* gs   = (const float*)d_in[1];
    const unsigned char* mask = (const unsigned char*)d_in[2];
    const int*   cseq = (const int*)d_in[3];
    const float* Wq = (const float*)d_in[4],  *bq = (const float*)d_in[5];
    const float* Wk = (const float*)d_in[6],  *bk = (const float*)d_in[7];
    const float* Wv = (const float*)d_in[8],  *bv = (const float*)d_in[9];
    const float* Wo = (const float*)d_in[10], *bo = (const float*)d_in[11];
    const float* lng = (const float*)d_in[12], *lnb = (const float*)d_in[13];
    const float* Wt = (const float*)d_in[14], *bt = (const float*)d_in[15];
    const float* Wgen = (const float*)d_in[16], *bgen = (const float*)d_in[17];
    const float* Wdiv = (const float*)d_in[18], *bdiv = (const float*)d_in[19];
    float* out = (float*)d_out;

    float* sc = nullptr;
    cudaGetSymbolAddress((void**)&sc, g_scratch);
    float* q     = sc + OQ;
    float* k     = sc + OK_;
    float* v     = sc + OV;
    float* vt    = sc + OVT;
    float* attn  = sc + OA;
    float* ctx   = sc + OC;
    float* ln    = sc + OL;
    float* tok   = sc + OT;
    float* gts   = sc + OG;
    float* rowsum = sc + ORS;
    __half* wgen_h = (__half*)(sc + OWB);
    __half* tok_h  = (__half*)(sc + OTB);

    const float scale = 0.044194173824159216f; // 1/sqrt(512)
    constexpr int SMEM  = 65536;
    cudaFuncSetAttribute(mma_nt_kernel<0>, cudaFuncAttributeMaxDynamicSharedMemorySize, SMEM);
    cudaFuncSetAttribute(mma_nt_kernel<1>, cudaFuncAttributeMaxDynamicSharedMemorySize, SMEM);
    cudaFuncSetAttribute(mma_f16_nt_kernel, cudaFuncAttributeMaxDynamicSharedMemorySize, SMEM);
    dim3 blk(256);
    dim3 blkG(128);

    // Side streams + events (created once on the uncaptured correctness call).
    static cudaStream_t s2 = [] { cudaStream_t s; cudaStreamCreate(&s); return s; }();
    static cudaStream_t s3 = [] { cudaStream_t s; cudaStreamCreate(&s); return s; }();
    static cudaEvent_t evFork = [] { cudaEvent_t e; cudaEventCreateWithFlags(&e, cudaEventDisableTiming); return e; }();
    static cudaEvent_t evWgen = [] { cudaEvent_t e; cudaEventCreateWithFlags(&e, cudaEventDisableTiming); return e; }();
    static cudaEvent_t evQ    = [] { cudaEvent_t e; cudaEventCreateWithFlags(&e, cudaEventDisableTiming); return e; }();
    static cudaEvent_t evV    = [] { cudaEvent_t e; cudaEventCreateWithFlags(&e, cudaEventDisableTiming); return e; }();
    static cudaEvent_t evVT   = [] { cudaEvent_t e; cudaEventCreateWithFlags(&e, cudaEventDisableTiming); return e; }();
    static cudaEvent_t evG0   = [] { cudaEvent_t e; cudaEventCreateWithFlags(&e, cudaEventDisableTiming); return e; }();
    static cudaEvent_t evS0   = [] { cudaEvent_t e; cudaEventCreateWithFlags(&e, cudaEventDisableTiming); return e; }();

    // fork from main
    cudaEventRecord(evFork, 0);
    cudaStreamWaitEvent(s2, evFork, 0);
    cudaStreamWaitEvent(s3, evFork, 0);

    // s2: Wgen->f16 + rowsum=0 (overlaps q/k/v GEMMs)
    f2h_kernel<<<(V_ * TS_ / 4 + 255) / 256, blk, 0, s2>>>((const float4*)Wgen, (__half2*)wgen_h, V_ * TS_ / 4);
    zero_kernel<<<SB / 256, blk, 0, s2>>>(rowsum);
    cudaEventRecord(evWgen, s2);

    // s3: q = (outs @ Wq^T + bq) * scale  (concurrent with k/v on main)
    mma_nt_kernel<0><<<dim3(4, 16, 1), blkG, SMEM, s3>>>(outs, Wq, bq, q, nullptr, D_, D_, D_, D_, 0, 0, 0, scale);
    cudaEventRecord(evQ, s3);

    // main: k and v GEMMs
    mma_nt_kernel<0><<<dim3(4, 64, 1), blkG, SMEM>>>(gs, Wk, bk, k, nullptr, D_, D_, D_, D_, 0, 0, 0, 1.f);
    mma_nt_kernel<0><<<dim3(4, 64, 1), blkG, SMEM>>>(gs, Wv, bv, v, nullptr, D_, D_, D_, D_, 0, 0, 0, 1.f);
    cudaEventRecord(evV, 0);

    // s3: v transpose (after v; overlaps scores+softmax on main)
    cudaStreamWaitEvent(s3, evV, 0);
    vt_kernel<<<dim3(32, 16, 8), blk, 0, s3>>>(v, vt);
    cudaEventRecord(evVT, s3);

    // main: join q, then scores + softmax
    cudaStreamWaitEvent(0, evQ, 0);
    mma_nt_kernel<0><<<dim3(8, 2, 8), blkG, SMEM>>>(q, k, nullptr, attn, nullptr,
                                                    D_, B_ * D_, B_ * D_, B_ * T_,
                                                    D_, D_, T_, 1.f);
    attn_softmax_kernel<<<SB, 256>>>(attn, mask);

    // join vt, then ctx = attn @ v  (NT vs v_T, batched over b)
    cudaStreamWaitEvent(0, evVT, 0);
    mma_nt_kernel<0><<<dim3(4, 2, 8), blkG, SMEM>>>(attn, vt, nullptr, ctx, nullptr,
                                                    T_, B_ * T_, T_, B_ * D_,
                                                    T_, (long)D_ * T_, D_, 1.f);
    // x = ctx @ Wo^T + bo   -> reuse q buffer
    mma_nt_kernel<0><<<dim3(4, 16, 1), blkG, SMEM>>>(ctx, Wo, bo, q, nullptr, D_, D_, D_, D_, 0, 0, 0, 1.f);
    // outs_ln = LN(outs + x)
    ln_kernel<<<SB, 256>>>(outs, q, lng, lnb, ln);
    // tok = tanh(outs_ln @ Wt^T + bt); fused f16 emit
    mma_nt_kernel<1><<<dim3(4, 16, 1), blkG, SMEM>>>(ln, Wt, bt, tok, tok_h, D_, D_, D_, TS_, 0, 0, 0, 1.f);
    // gates
    gates_kernel<<<SB, 128>>>(tok, Wdiv, bdiv, gts);

    // join Wgen conversion + rowsum init, then vocab GEMM split in M-halves
    cudaStreamWaitEvent(0, evWgen, 0);
    constexpr int MH = SB / 2;  // 1024 rows per half
    // half 0 (rows 0..1023)
    mma_f16_nt_kernel<<<dim3(250, 8, 1), blkG, SMEM>>>(tok_h, wgen_h, bgen, out, rowsum,
                                                       TS_, TS_, TS_, V_);
    cudaEventRecord(evG0, 0);
    // half 1 (rows 1024..2047) on main
    mma_f16_nt_kernel<<<dim3(250, 8, 1), blkG, SMEM>>>(tok_h + (long)MH * TS_, wgen_h, bgen,
                                                       out + (long)MH * V_, rowsum + MH,
                                                       TS_, TS_, TS_, V_);
    // s2: scatter half 0 overlaps GEMM half 1
    cudaStreamWaitEvent(s2, evG0, 0);
    lp_scatter_kernel<<<MH, 256, 0, s2>>>(out, rowsum, gts, attn, cseq);
    cudaEventRecord(evS0, s2);
    // main: scatter half 1, then join s2
    lp_scatter_kernel<<<MH, 256>>>(out + (long)MH * V_, rowsum + MH, gts + 2 * MH,
                                   attn + (long)MH * T_, cseq);
    cudaStreamWaitEvent(0, evS0, 0);
}

// round 15
// speedup vs baseline: 1.0363x; 1.0363x over previous
#include <cuda_runtime.h>
#include <cuda_fp16.h>
#include <math.h>
#include <stdint.h>

// Problem dims (fixed for this dataset)
constexpr int S_  = 256;
constexpr int B_  = 8;
constexpr int T_  = 1024;
constexpr int D_  = 512;
constexpr int TS_ = 512;
constexpr int V_  = 32000;
constexpr int SB  = S_ * B_;   // 2048
constexpr int TB  = T_ * B_;   // 8192

// ---------------------------------------------------------------------------
// Scratch arena
// ---------------------------------------------------------------------------
constexpr size_t OQ  = 0;                        // q / later x      : SB*D
constexpr size_t OK_ = OQ  + (size_t)SB * D_;    // k                : TB*D
constexpr size_t OV  = OK_ + (size_t)TB * D_;    // v                : TB*D
constexpr size_t OVT = OV  + (size_t)TB * D_;    // v transposed     : TB*D
constexpr size_t OA  = OVT + (size_t)TB * D_;    // attn (exp scores): SB*T
constexpr size_t OC  = OA  + (size_t)SB * T_;    // ctx              : SB*D
constexpr size_t OL  = OC  + (size_t)SB * D_;    // layernorm out    : SB*D
constexpr size_t OT  = OL  + (size_t)SB * D_;    // outs_token (f32) : SB*D
constexpr size_t OG  = OT  + (size_t)SB * D_;    // gates            : SB*2
constexpr size_t ORS = OG  + (size_t)SB * 2;     // rowsum exp(logit): SB
constexpr size_t OZ  = ORS + SB;                 // attn Z (exp sums): SB
constexpr size_t OWB = OZ  + SB;                 // Wgen f16         : V*TS/2 floats
constexpr size_t OTB = OWB + (size_t)V_ * TS_ / 2;  // tok f16       : SB*TS/2
constexpr size_t SCRATCH_FLOATS = OTB + (size_t)SB * TS_ / 2;

__device__ float g_scratch[SCRATCH_FLOATS];

// ---------------------------------------------------------------------------
// math helpers
// ---------------------------------------------------------------------------
__device__ __forceinline__ float fexp(float x) {
    float t = fmaxf(fminf(x * 1.4426950408889634f, 126.f), -126.f);
    float mg = t + 12582912.f;
    int   n  = __float_as_int(mg) - 0x4B400000;
    float f  = t - (mg - 12582912.f);
    float p  = 1.54035304e-4f;
    p = fmaf(p, f, 1.33335581e-3f);
    p = fmaf(p, f, 9.61812911e-3f);
    p = fmaf(p, f, 5.55041087e-2f);
    p = fmaf(p, f, 2.40226507e-1f);
    p = fmaf(p, f, 6.93147182e-1f);
    p = fmaf(p, f, 1.0f);
    return __int_as_float(__float_as_int(p) + (n << 23));
}

__device__ __forceinline__ void mma_tf32(float& c0, float& c1, float& c2, float& c3,
                                         unsigned a0, unsigned a1, unsigned a2, unsigned a3,
                                         unsigned b0, unsigned b1)
{
    asm volatile(
        "mma.sync.aligned.m16n8k8.row.col.f32.tf32.tf32.f32 "
        "{%0,%1,%2,%3}, {%4,%5,%6,%7}, {%8,%9}, {%0,%1,%2,%3};"
        : "+f"(c0), "+f"(c1), "+f"(c2), "+f"(c3)
        : "r"(a0), "r"(a1), "r"(a2), "r"(a3), "r"(b0), "r"(b1));
}

__device__ __forceinline__ void mma_f16f32(float& c0, float& c1, float& c2, float& c3,
                                           unsigned a0, unsigned a1, unsigned a2, unsigned a3,
                                           unsigned b0, unsigned b1)
{
    asm volatile(
        "mma.sync.aligned.m16n8k16.row.col.f32.f16.f16.f32 "
        "{%0,%1,%2,%3}, {%4,%5,%6,%7}, {%8,%9}, {%0,%1,%2,%3};"
        : "+f"(c0), "+f"(c1), "+f"(c2), "+f"(c3)
        : "r"(a0), "r"(a1), "r"(a2), "r"(a3), "r"(b0), "r"(b1));
}

__device__ __forceinline__ void ldsm_x4(unsigned& r0, unsigned& r1, unsigned& r2, unsigned& r3,
                                        unsigned addr)
{
    asm volatile("ldmatrix.sync.aligned.m8n8.x4.shared.b16 {%0,%1,%2,%3}, [%4];"
                 : "=r"(r0), "=r"(r1), "=r"(r2), "=r"(r3) : "r"(addr));
}

__device__ __forceinline__ void cp16(unsigned dst, const void* src) {
    asm volatile("cp.async.cg.shared.global [%0], [%1], 16;\n" :: "r"(dst), "l"(src));
}

// ---------------------------------------------------------------------------
// Tensor-core NT GEMM (tf32): 128x128 block, 4 warps, warp tile 64x64, BK=32,
// 64KB SMEM, 2 CTAs/SM, single sync per k-iter.
// ACT=0: C = alpha*(AB^T + bias)
// ACT=1: C = tanh(...), also emits f16 copy to Ch
// ACT=2: scores->exp: C = mask ? 0 : exp(AB^T); atomicAdd row sums into Zb
//        (Z index = m_row * B + blockIdx.z)
// ACT=3: ctx scale: C = (AB^T) * (1/Zb[m_row*B + blockIdx.z])
// ---------------------------------------------------------------------------
template <int ACT>
__global__ __launch_bounds__(128, 2)
void mma_nt_kernel(const float* __restrict__ A, const float* __restrict__ Bm,
                   const float* __restrict__ bias, float* __restrict__ C,
                   __half* __restrict__ Ch,
                   const unsigned char* __restrict__ mk, float* __restrict__ Zb,
                   int K, int lda, int ldb, int ldc,
                   long sA, long sB, long sC, float alpha)
{
    extern __shared__ unsigned sh[];

    A  += (long)blockIdx.z * sA;
    Bm += (long)blockIdx.z * sB;
    C  += (long)blockIdx.z * sC;

    const int t    = threadIdx.x;
    const int lane = t & 31;
    const int warp = t >> 5;
    const int wm   = (warp >> 1) * 64;
    const int wn   = (warp & 1) * 64;
    const int grp  = lane >> 2;
    const int qid  = lane & 3;

    const long m0 = (long)blockIdx.y * 128;
    const long n0 = (long)blockIdx.x * 128;

    float acc[4][8][4];
#pragma unroll
    for (int mi = 0; mi < 4; mi++)
#pragma unroll
        for (int ni = 0; ni < 8; ni++)
#pragma unroll
            for (int c = 0; c < 4; c++) acc[mi][ni][c] = 0.f;

    const int row0 = t >> 3;
    const int c4   = t & 7;
    const float* aptr0 = A  + (m0 + row0) * lda + c4 * 4;
    const float* bptr0 = Bm + (n0 + row0) * ldb + c4 * 4;
    const unsigned soff0 = (unsigned)(row0 * 32 + ((c4 ^ (row0 & 7)) << 2)) * 4u;
    const unsigned sbase = (unsigned)__cvta_generic_to_shared(sh);

    auto issue = [&](int stage, int koff) {
        unsigned ab = sbase + (unsigned)stage * 16384u + soff0;
        unsigned bb = sbase + 32768u + (unsigned)stage * 16384u + soff0;
#pragma unroll
        for (int i = 0; i < 8; i++) {
            cp16(ab + i * 2048u, aptr0 + (long)i * 16 * lda + koff);
            cp16(bb + i * 2048u, bptr0 + (long)i * 16 * ldb + koff);
        }
        asm volatile("cp.async.commit_group;\n" ::: "memory");
    };

    issue(0, 0);
    const int nIter = K >> 5;
    for (int it = 0; it < nIter; ++it) {
        asm volatile("cp.async.wait_group 0;\n" ::: "memory");
        __syncthreads();
        if (it + 1 < nIter) issue((it + 1) & 1, (it + 1) * 32);

        const unsigned* Asb = sh + (it & 1) * 4096;
        const unsigned* Bsb = sh + 8192 + (it & 1) * 4096;
#pragma unroll
        for (int kk = 0; kk < 4; kk++) {
            unsigned af[4][4], bf[8][2];
#pragma unroll
            for (int mi = 0; mi < 4; mi++) {
                int m  = wm + mi * 16 + grp;
                int m8 = m + 8;
                af[mi][0] = Asb[m  * 32 + ((( kk * 2    ) ^ (m  & 7)) << 2) + qid];
                af[mi][1] = Asb[m8 * 32 + ((( kk * 2    ) ^ (m8 & 7)) << 2) + qid];
                af[mi][2] = Asb[m  * 32 + ((( kk * 2 + 1) ^ (m  & 7)) << 2) + qid];
                af[mi][3] = Asb[m8 * 32 + ((( kk * 2 + 1) ^ (m8 & 7)) << 2) + qid];
            }
#pragma unroll
            for (int ni = 0; ni < 8; ni++) {
                int n = wn + ni * 8 + grp;
                bf[ni][0] = Bsb[n * 32 + ((( kk * 2    ) ^ (n & 7)) << 2) + qid];
                bf[ni][1] = Bsb[n * 32 + ((( kk * 2 + 1) ^ (n & 7)) << 2) + qid];
            }
#pragma unroll
            for (int mi = 0; mi < 4; mi++)
#pragma unroll
                for (int ni = 0; ni < 8; ni++)
                    mma_tf32(acc[mi][ni][0], acc[mi][ni][1], acc[mi][ni][2], acc[mi][ni][3],
                             af[mi][0], af[mi][1], af[mi][2], af[mi][3],
                             bf[ni][0], bf[ni][1]);
        }
    }

#pragma unroll
    for (int mi = 0; mi < 4; mi++) {
        long r0 = m0 + wm + mi * 16 + grp;
        long r1 = r0 + 8;
        float e0 = 0.f, e1 = 0.f;       // ACT==2 row sums
        float iz0 = 1.f, iz1 = 1.f;     // ACT==3 row scales
        if (ACT == 3) {
            iz0 = 1.f / Zb[r0 * B_ + blockIdx.z];
            iz1 = 1.f / Zb[r1 * B_ + blockIdx.z];
        }
#pragma unroll
        for (int ni = 0; ni < 8; ni++) {
            long col = n0 + wn + ni * 8 + qid * 2;
            float bv0 = 0.f, bv1 = 0.f;
            if (bias) { bv0 = bias[col]; bv1 = bias[col + 1]; }
            float v00 = (acc[mi][ni][0] + bv0) * alpha;
            float v01 = (acc[mi][ni][1] + bv1) * alpha;
            float v10 = (acc[mi][ni][2] + bv0) * alpha;
            float v11 = (acc[mi][ni][3] + bv1) * alpha;
            if (ACT == 1) { v00 = tanhf(v00); v01 = tanhf(v01); v10 = tanhf(v10); v11 = tanhf(v11); }
            if (ACT == 2) {
                v00 = mk[col]     ? 0.f : fexp(v00);
                v01 = mk[col + 1] ? 0.f : fexp(v01);
                v10 = mk[col]     ? 0.f : fexp(v10);
                v11 = mk[col + 1] ? 0.f : fexp(v11);
                e0 += v00 + v01;
                e1 += v10 + v11;
            }
            if (ACT == 3) { v00 *= iz0; v01 *= iz0; v10 *= iz1; v11 *= iz1; }
            *(float2*)(C + r0 * ldc + col) = make_float2(v00, v01);
            *(float2*)(C + r1 * ldc + col) = make_float2(v10, v11);
            if (ACT == 1 && Ch) {
                *(__half2*)(Ch + r0 * ldc + col) = __floats2half2_rn(v00, v01);
                *(__half2*)(Ch + r1 * ldc + col) = __floats2half2_rn(v10, v11);
            }
        }
        if (ACT == 2) {
            e0 += __shfl_xor_sync(0xFFFFFFFFu, e0, 1);
            e0 += __shfl_xor_sync(0xFFFFFFFFu, e0, 2);
            e1 += __shfl_xor_sync(0xFFFFFFFFu, e1, 1);
            e1 += __shfl_xor_sync(0xFFFFFFFFu, e1, 2);
            if (qid == 0) {
                atomicAdd(Zb + r0 * B_ + blockIdx.z, e0);
                atomicAdd(Zb + r1 * B_ + blockIdx.z, e1);
            }
        }
    }
}

// ---------------------------------------------------------------------------
// f16-input/f32-accum NT GEMM + fused exp-rowsum: 128x128 block, 4 warps,
// warp 64x64, BK=64, 2-stage cp.async (64KB SMEM), ldmatrix.x4, 3 CTAs/SM.
// ---------------------------------------------------------------------------
__global__ __launch_bounds__(128, 3)
void mma_f16_nt_kernel(const __half* __restrict__ A,
                       const __half* __restrict__ Bm,
                       const float* __restrict__ bias, float* __restrict__ C,
                       float* __restrict__ rowsum,
                       int K, int lda, int ldb, int ldc)
{
    extern __shared__ unsigned sh[];

    const int t    = threadIdx.x;
    const int lane = t & 31;
    const int warp = t >> 5;
    const int wm   = (warp >> 1) * 64;
    const int wn   = (warp & 1) * 64;
    const int grp  = lane >> 2;
    const int qid  = lane & 3;

    const long m0 = (long)blockIdx.y * 128;
    const long n0 = (long)blockIdx.x * 128;

    float acc[4][8][4];
#pragma unroll
    for (int mi = 0; mi < 4; mi++)
#pragma unroll
        for (int ni = 0; ni < 8; ni++)
#pragma unroll
            for (int c = 0; c < 4; c++) acc[mi][ni][c] = 0.f;

    const int row0 = t >> 3;
    const int c8   = t & 7;
    const __half* aptr0 = A  + (m0 + row0) * lda + c8 * 8;
    const __half* bptr0 = Bm + (n0 + row0) * ldb + c8 * 8;
    const unsigned soff0 = (unsigned)(row0 * 128 + ((c8 ^ (row0 & 7)) << 4));
    const unsigned sbase = (unsigned)__cvta_generic_to_shared(sh);

    const int a_lr = lane & 15;
    const int a_cs = lane >> 4;
    unsigned a_off[4]; int a_m7[4];
#pragma unroll
    for (int mi = 0; mi < 4; mi++) {
        int m = wm + mi * 16 + a_lr;
        a_off[mi] = (unsigned)(m * 128);
        a_m7[mi]  = m & 7;
    }
    const int b_g  = lane >> 3;
    const int b_cs = b_g & 1;
    unsigned b_off[4]; int b_n7[4];
#pragma unroll
    for (int p = 0; p < 4; p++) {
        int n = wn + p * 16 + ((b_g & 2) << 2) + (lane & 7);
        b_off[p] = (unsigned)(n * 128);
        b_n7[p]  = n & 7;
    }

    auto issue = [&](int stage, int koff) {
        unsigned ab = sbase + (unsigned)stage * 32768u + soff0;
        unsigned bb = ab + 16384u;
#pragma unroll
        for (int i = 0; i < 8; i++) {
            cp16(ab + i * 2048u, aptr0 + (long)i * 16 * lda + koff);
            cp16(bb + i * 2048u, bptr0 + (long)i * 16 * ldb + koff);
        }
        asm volatile("cp.async.commit_group;\n" ::: "memory");
    };

    const int nIter = K >> 6;
    issue(0, 0);
    for (int it = 0; it < nIter; ++it) {
        asm volatile("cp.async.wait_group 0;\n" ::: "memory");
        __syncthreads();
        if (it + 1 < nIter) issue((it + 1) & 1, (it + 1) * 64);

        unsigned abase = sbase + (unsigned)(it & 1) * 32768u;
        unsigned bbase = abase + 16384u;
#pragma unroll
        for (int kk = 0; kk < 4; kk++) {
            unsigned af[4][4], bf[8][2];
            int ca = kk * 2 + a_cs;
            int cb = kk * 2 + b_cs;
#pragma unroll
            for (int mi = 0; mi < 4; mi++) {
                unsigned addr = abase + a_off[mi] + (unsigned)((ca ^ a_m7[mi]) << 4);
                ldsm_x4(af[mi][0], af[mi][1], af[mi][2], af[mi][3], addr);
            }
#pragma unroll
            for (int p = 0; p < 4; p++) {
                unsigned addr = bbase + b_off[p] + (unsigned)((cb ^ b_n7[p]) << 4);
                ldsm_x4(bf[2*p][0], bf[2*p][1], bf[2*p+1][0], bf[2*p+1][1], addr);
            }
#pragma unroll
            for (int mi = 0; mi < 4; mi++)
#pragma unroll
                for (int ni = 0; ni < 8; ni++)
                    mma_f16f32(acc[mi][ni][0], acc[mi][ni][1], acc[mi][ni][2], acc[mi][ni][3],
                               af[mi][0], af[mi][1], af[mi][2], af[mi][3],
                               bf[ni][0], bf[ni][1]);
        }
    }

    // epilogue: write logits + per-row sum of exp
#pragma unroll
    for (int mi = 0; mi < 4; mi++) {
        long r0 = m0 + wm + mi * 16 + grp;
        long r1 = r0 + 8;
        float e0 = 0.f, e1 = 0.f;
#pragma unroll
        for (int ni = 0; ni < 8; ni++) {
            long col = n0 + wn + ni * 8 + qid * 2;
            float bv0 = bias[col], bv1 = bias[col + 1];
            float v00 = acc[mi][ni][0] + bv0;
            float v01 = acc[mi][ni][1] + bv1;
            float v10 = acc[mi][ni][2] + bv0;
            float v11 = acc[mi][ni][3] + bv1;
            *(float2*)(C + r0 * ldc + col) = make_float2(v00, v01);
            *(float2*)(C + r1 * ldc + col) = make_float2(v10, v11);
            e0 += fexp(v00) + fexp(v01);
            e1 += fexp(v10) + fexp(v11);
        }
        e0 += __shfl_xor_sync(0xFFFFFFFFu, e0, 1);
        e0 += __shfl_xor_sync(0xFFFFFFFFu, e0, 2);
        e1 += __shfl_xor_sync(0xFFFFFFFFu, e1, 1);
        e1 += __shfl_xor_sync(0xFFFFFFFFu, e1, 2);
        if (qid == 0) {
            atomicAdd(rowsum + r0, e0);
            atomicAdd(rowsum + r1, e1);
        }
    }
}

// ---------------------------------------------------------------------------
// fp32 -> f16 convert
// ---------------------------------------------------------------------------
__global__ __launch_bounds__(256)
void f2h_kernel(const float4* __restrict__ in, __half2* __restrict__ out, int n4)
{
    int i = blockIdx.x * 256 + threadIdx.x;
    if (i >= n4) return;
    float4 v = in[i];
    out[i * 2]     = __floats2half2_rn(v.x, v.y);
    out[i * 2 + 1] = __floats2half2_rn(v.z, v.w);
}

__global__ void zero_kernel(float* __restrict__ p)
{
    p[blockIdx.x * 256 + threadIdx.x] = 0.f;
}

// ---------------------------------------------------------------------------
// v transpose: vt[b][d][t] = v[(t*B+b)*D + d].
// ---------------------------------------------------------------------------
__global__ __launch_bounds__(256)
void vt_kernel(const float* __restrict__ v, float* __restrict__ vt)
{
    __shared__ float tile[32][33];
    int b  = blockIdx.z;
    int t0 = blockIdx.x * 32;
    int d0 = blockIdx.y * 32;
    int x  = threadIdx.x & 31;
    int y  = threadIdx.x >> 5;
#pragma unroll
    for (int j = 0; j < 32; j += 8)
        tile[y + j][x] = v[((long)(t0 + y + j) * B_ + b) * D_ + d0 + x];
    __syncthreads();
#pragma unroll
    for (int j = 0; j < 32; j += 8)
        vt[(long)b * D_ * T_ + (long)(d0 + y + j) * T_ + t0 + x] = tile[x][y + j];
}

// ---------------------------------------------------------------------------
// LayerNorm(outs + x).
// ---------------------------------------------------------------------------
__global__ __launch_bounds__(256)
void ln_kernel(const float* __restrict__ outs, const float* __restrict__ x,
               const float* __restrict__ g, const float* __restrict__ bb,
               float* __restrict__ out)
{
    int row = blockIdx.x;
    int t = threadIdx.x;
    const float* o  = outs + (long)row * D_;
    const float* xr = x    + (long)row * D_;
    __shared__ float red[256];

    float v0 = o[t] + xr[t];
    float v1 = o[t + 256] + xr[t + 256];

    red[t] = v0 + v1; __syncthreads();
    for (int s = 128; s > 0; s >>= 1) { if (t < s) red[t] += red[t + s]; __syncthreads(); }
    float mu = red[0] * (1.f / D_); __syncthreads();

    float d0 = v0 - mu, d1 = v1 - mu;
    red[t] = d0 * d0 + d1 * d1; __syncthreads();
    for (int s = 128; s > 0; s >>= 1) { if (t < s) red[t] += red[t + s]; __syncthreads(); }
    float inv = rsqrtf(red[0] * (1.f / D_) + 1e-5f);

    out[(long)row * D_ + t]       = d0 * inv * g[t]       + bb[t];
    out[(long)row * D_ + t + 256] = d1 * inv * g[t + 256] + bb[t + 256];
}

// ---------------------------------------------------------------------------
// 2-way gate
// ---------------------------------------------------------------------------
__global__ __launch_bounds__(128)
void gates_kernel(const float* __restrict__ tok, const float* __restrict__ Wdiv,
                  const float* __restrict__ bdiv, float* __restrict__ gates)
{
    int row = blockIdx.x;
    int t = threadIdx.x;
    const float* x = tok + (long)row * D_;
    float z0 = 0.f, z1 = 0.f;
    for (int d = t; d < D_; d += 128) {
        float xv = x[d];
        z0 = fmaf(xv, Wdiv[d],      z0);
        z1 = fmaf(xv, Wdiv[D_ + d], z1);
    }
    __shared__ float r0[128], r1[128];
    r0[t] = z0; r1[t] = z1; __syncthreads();
    for (int s = 64; s > 0; s >>= 1) {
        if (t < s) { r0[t] += r0[t + s]; r1[t] += r1[t + s]; }
        __syncthreads();
    }
    if (t == 0) {
        float a = r0[0] + bdiv[0], b = r1[0] + bdiv[1];
        float m = fmaxf(a, b);
        float e0 = __expf(a - m), e1 = __expf(b - m);
        float inv = 1.f / (e0 + e1);
        gates[row * 2 + 0] = e0 * inv;
        gates[row * 2 + 1] = e1 * inv;
    }
}

// ---------------------------------------------------------------------------
// Fused coef + log-prob base + copy-scatter. One block (256 thr) per row.
// attn holds UNNORMALIZED exp(scores); zsum holds per-row Z.
// Pointers pre-offset by the caller for row-range splitting (base % 8 == 0).
// ---------------------------------------------------------------------------
__global__ __launch_bounds__(256)
void lp_scatter_kernel(float* __restrict__ out, const float* __restrict__ rowsum,
                       const float* __restrict__ gates, const float* __restrict__ attn,
                       const float* __restrict__ zsum, const int* __restrict__ copy_seq)
{
    int row = blockIdx.x;
    int t   = threadIdx.x;
    int b   = row & (B_ - 1);

    float coef = __logf(gates[row * 2 + 0]) - __logf(rowsum[row]);
    float gate1z = gates[row * 2 + 1] / zsum[row];

    float4* o4 = (float4*)(out + (long)row * V_);
    for (int j = t; j < V_ / 4; j += 256) {
        float4 v = o4[j];
        v.x += coef; v.y += coef; v.z += coef; v.w += coef;
        o4[j] = v;
    }
    __syncthreads();

    const float* arow = attn + (long)row * T_;
    float* orow = out + (long)row * V_;
#pragma unroll
    for (int e = 0; e < 4; e++) {
        int tt = t + e * 256;
        float val = gate1z * arow[tt];
        int idx = copy_seq[tt * B_ + b];
        int* ia = (int*)(orow + idx);
        int assumed = *ia;
        int old;
        do {
            old = assumed;
            float cur = __int_as_float(old);
            float nv = __logf(__expf(cur) + val);
            assumed = atomicCAS(ia, old, __float_as_int(nv));
        } while (assumed != old);
    }
}

// ---------------------------------------------------------------------------
// Launch
// ---------------------------------------------------------------------------
extern "C" void kernel_launch(void* const* d_in, const int* in_sizes, int n_in,
                              void* d_out, int out_size)
{
    const float* outs = (const float*)d_in[0];
    const float* gs   = (const float*)d_in[1];
    const unsigned char* mask = (const unsigned char*)d_in[2];
    const int*   cseq = (const int*)d_in[3];
    const float* Wq = (const float*)d_in[4],  *bq = (const float*)d_in[5];
    const float* Wk = (const float*)d_in[6],  *bk = (const float*)d_in[7];
    const float* Wv = (const float*)d_in[8],  *bv = (const float*)d_in[9];
    const float* Wo = (const float*)d_in[10], *bo = (const float*)d_in[11];
    const float* lng = (const float*)d_in[12], *lnb = (const float*)d_in[13];
    const float* Wt = (const float*)d_in[14], *bt = (const float*)d_in[15];
    const float* Wgen = (const float*)d_in[16], *bgen = (const float*)d_in[17];
    const float* Wdiv = (const float*)d_in[18], *bdiv = (const float*)d_in[19];
    float* out = (float*)d_out;

    float* sc = nullptr;
    cudaGetSymbolAddress((void**)&sc, g_scratch);
    float* q     = sc + OQ;
    float* k     = sc + OK_;
    float* v     = sc + OV;
    float* vt    = sc + OVT;
    float* attn  = sc + OA;
    float* ctx   = sc + OC;
    float* ln    = sc + OL;
    float* tok   = sc + OT;
    float* gts   = sc + OG;
    float* rowsum = sc + ORS;   // rowsum (SB) + attn-Z (SB) contiguous
    float* zattn  = sc + OZ;
    __half* wgen_h = (__half*)(sc + OWB);
    __half* tok_h  = (__half*)(sc + OTB);

    const float scale = 0.044194173824159216f; // 1/sqrt(512)
    constexpr int SMEM  = 65536;
    cudaFuncSetAttribute(mma_nt_kernel<0>, cudaFuncAttributeMaxDynamicSharedMemorySize, SMEM);
    cudaFuncSetAttribute(mma_nt_kernel<1>, cudaFuncAttributeMaxDynamicSharedMemorySize, SMEM);
    cudaFuncSetAttribute(mma_nt_kernel<2>, cudaFuncAttributeMaxDynamicSharedMemorySize, SMEM);
    cudaFuncSetAttribute(mma_nt_kernel<3>, cudaFuncAttributeMaxDynamicSharedMemorySize, SMEM);
    cudaFuncSetAttribute(mma_f16_nt_kernel, cudaFuncAttributeMaxDynamicSharedMemorySize, SMEM);
    dim3 blk(256);
    dim3 blkG(128);

    static cudaStream_t s2 = [] { cudaStream_t s; cudaStreamCreate(&s); return s; }();
    static cudaStream_t s3 = [] { cudaStream_t s; cudaStreamCreate(&s); return s; }();
    static cudaEvent_t evFork = [] { cudaEvent_t e; cudaEventCreateWithFlags(&e, cudaEventDisableTiming); return e; }();
    static cudaEvent_t evWgen = [] { cudaEvent_t e; cudaEventCreateWithFlags(&e, cudaEventDisableTiming); return e; }();
    static cudaEvent_t evQ    = [] { cudaEvent_t e; cudaEventCreateWithFlags(&e, cudaEventDisableTiming); return e; }();
    static cudaEvent_t evV    = [] { cudaEvent_t e; cudaEventCreateWithFlags(&e, cudaEventDisableTiming); return e; }();
    static cudaEvent_t evVT   = [] { cudaEvent_t e; cudaEventCreateWithFlags(&e, cudaEventDisableTiming); return e; }();
    static cudaEvent_t evG0   = [] { cudaEvent_t e; cudaEventCreateWithFlags(&e, cudaEventDisableTiming); return e; }();
    static cudaEvent_t evG1   = [] { cudaEvent_t e; cudaEventCreateWithFlags(&e, cudaEventDisableTiming); return e; }();
    static cudaEvent_t evG2   = [] { cudaEvent_t e; cudaEventCreateWithFlags(&e, cudaEventDisableTiming); return e; }();
    static cudaEvent_t evS0   = [] { cudaEvent_t e; cudaEventCreateWithFlags(&e, cudaEventDisableTiming); return e; }();

    // fork from main
    cudaEventRecord(evFork, 0);
    cudaStreamWaitEvent(s2, evFork, 0);
    cudaStreamWaitEvent(s3, evFork, 0);

    // s2: Wgen->f16 + zero(rowsum & zattn) (overlaps q/k/v GEMMs)
    f2h_kernel<<<(V_ * TS_ / 4 + 255) / 256, blk, 0, s2>>>((const float4*)Wgen, (__half2*)wgen_h, V_ * TS_ / 4);
    zero_kernel<<<2 * SB / 256, blk, 0, s2>>>(rowsum);   // rowsum + zattn contiguous
    cudaEventRecord(evWgen, s2);

    // s3: q GEMM (concurrent with k/v on main)
    mma_nt_kernel<0><<<dim3(4, 16, 1), blkG, SMEM, s3>>>(outs, Wq, bq, q, nullptr, nullptr, nullptr,
                                                         D_, D_, D_, D_, 0, 0, 0, scale);
    cudaEventRecord(evQ, s3);

    // main: k and v GEMMs
    mma_nt_kernel<0><<<dim3(4, 64, 1), blkG, SMEM>>>(gs, Wk, bk, k, nullptr, nullptr, nullptr,
                                                     D_, D_, D_, D_, 0, 0, 0, 1.f);
    mma_nt_kernel<0><<<dim3(4, 64, 1), blkG, SMEM>>>(gs, Wv, bv, v, nullptr, nullptr, nullptr,
                                                     D_, D_, D_, D_, 0, 0, 0, 1.f);
    cudaEventRecord(evV, 0);

    // s3: v transpose (overlaps scores on main)
    cudaStreamWaitEvent(s3, evV, 0);
    vt_kernel<<<dim3(32, 16, 8), blk, 0, s3>>>(v, vt);
    cudaEventRecord(evVT, s3);

    // main: join q + zero(zattn), then scores with fused exp+Z (no softmax kernel)
    cudaStreamWaitEvent(0, evQ, 0);
    cudaStreamWaitEvent(0, evWgen, 0);
    mma_nt_kernel<2><<<dim3(8, 2, 8), blkG, SMEM>>>(q, k, nullptr, attn, nullptr, mask, zattn,
                                                    D_, B_ * D_, B_ * D_, B_ * T_,
                                                    D_, D_, T_, 1.f);

    // join vt, then ctx = (expS @ v) / Z  (NT vs v_T, batched over b)
    cudaStreamWaitEvent(0, evVT, 0);
    mma_nt_kernel<3><<<dim3(4, 2, 8), blkG, SMEM>>>(attn, vt, nullptr, ctx, nullptr, nullptr, zattn,
                                                    T_, B_ * T_, T_, B_ * D_,
                                                    T_, (long)D_ * T_, D_, 1.f);
    // x = ctx @ Wo^T + bo   -> reuse q buffer
    mma_nt_kernel<0><<<dim3(4, 16, 1), blkG, SMEM>>>(ctx, Wo, bo, q, nullptr, nullptr, nullptr,
                                                     D_, D_, D_, D_, 0, 0, 0, 1.f);
    // outs_ln = LN(outs + x)
    ln_kernel<<<SB, 256>>>(outs, q, lng, lnb, ln);
    // tok = tanh(outs_ln @ Wt^T + bt); fused f16 emit
    mma_nt_kernel<1><<<dim3(4, 16, 1), blkG, SMEM>>>(ln, Wt, bt, tok, tok_h, nullptr, nullptr,
                                                     D_, D_, D_, TS_, 0, 0, 0, 1.f);
    // gates
    gates_kernel<<<SB, 128>>>(tok, Wdiv, bdiv, gts);

    // vocab GEMM in 4 M-quarters, pipelined with lp_scatter
    constexpr int MQ = SB / 4;  // 512 rows per quarter
    cudaEvent_t evG[3] = {evG0, evG1, evG2};
    for (int qi = 0; qi < 4; qi++) {
        long ro = (long)qi * MQ;
        mma_f16_nt_kernel<<<dim3(250, MQ / 128, 1), blkG, SMEM>>>(
            tok_h + ro * TS_, wgen_h, bgen, out + ro * V_, rowsum + ro,
            TS_, TS_, TS_, V_);
        if (qi < 3) cudaEventRecord(evG[qi], 0);
    }
    // s2: scatter quarters 0..2 overlap GEMM quarters 1..3
    for (int qi = 0; qi < 3; qi++) {
        long ro = (long)qi * MQ;
        cudaStreamWaitEvent(s2, evG[qi], 0);
        lp_scatter_kernel<<<MQ, 256, 0, s2>>>(out + ro * V_, rowsum + ro, gts + 2 * ro,
                                              attn + ro * T_, zattn + ro, cseq);
    }
    cudaEventRecord(evS0, s2);
    // main: scatter last quarter, then join s2
    {
        long ro = 3L * MQ;
        lp_scatter_kernel<<<MQ, 256>>>(out + ro * V_, rowsum + ro, gts + 2 * ro,
                                       attn + ro * T_, zattn + ro, cseq);
    }
    cudaStreamWaitEvent(0, evS0, 0);
}

// round 16
// speedup vs baseline: 1.0799x; 1.0420x over previous
#include <cuda_runtime.h>
#include <cuda_fp16.h>
#include <math.h>
#include <stdint.h>

// Problem dims (fixed for this dataset)
constexpr int S_  = 256;
constexpr int B_  = 8;
constexpr int T_  = 1024;
constexpr int D_  = 512;
constexpr int TS_ = 512;
constexpr int V_  = 32000;
constexpr int SB  = S_ * B_;   // 2048
constexpr int TB  = T_ * B_;   // 8192

// ---------------------------------------------------------------------------
// Scratch arena (f32 slots; __half buffers use half the slots)
// ---------------------------------------------------------------------------
constexpr size_t OX   = 0;                        // x (attn residual) f32 : SB*D
constexpr size_t OTOK = OX   + (size_t)SB * D_;   // tok f32              : SB*D
constexpr size_t OG   = OTOK + (size_t)SB * D_;   // gates                : SB*2
constexpr size_t ORS  = OG   + (size_t)SB * 2;    // rowsum exp(logit)    : SB
constexpr size_t OZ   = ORS  + SB;                // attn Z               : SB
constexpr size_t OOH  = OZ   + SB;                       // outs_h  : SB*D/2
constexpr size_t OGH  = OOH  + (size_t)SB * D_ / 2;      // gs_h    : TB*D/2
constexpr size_t OWQ  = OGH  + (size_t)TB * D_ / 2;      // wq_h    : D*D/2
constexpr size_t OWK  = OWQ  + (size_t)D_ * D_ / 2;
constexpr size_t OWV  = OWK  + (size_t)D_ * D_ / 2;
constexpr size_t OWO  = OWV  + (size_t)D_ * D_ / 2;
constexpr size_t OWT  = OWO  + (size_t)D_ * D_ / 2;
constexpr size_t OQH  = OWT  + (size_t)D_ * D_ / 2;      // q_h     : SB*D/2
constexpr size_t OKH  = OQH  + (size_t)SB * D_ / 2;      // k_h     : TB*D/2
constexpr size_t OVH  = OKH  + (size_t)TB * D_ / 2;      // v_h     : TB*D/2
constexpr size_t OVT  = OVH  + (size_t)TB * D_ / 2;      // vt_h    : TB*D/2
constexpr size_t OAH  = OVT  + (size_t)TB * D_ / 2;      // attn_h  : SB*T/2
constexpr size_t OCH  = OAH  + (size_t)SB * T_ / 2;      // ctx_h   : SB*D/2
constexpr size_t OLH  = OCH  + (size_t)SB * D_ / 2;      // ln_h    : SB*D/2
constexpr size_t OTH  = OLH  + (size_t)SB * D_ / 2;      // tok_h   : SB*TS/2
constexpr size_t OWG  = OTH  + (size_t)SB * TS_ / 2;     // wgen_h  : V*TS/2
constexpr size_t SCRATCH_FLOATS = OWG + (size_t)V_ * TS_ / 2;

__device__ float g_scratch[SCRATCH_FLOATS];

// ---------------------------------------------------------------------------
// math helpers
// ---------------------------------------------------------------------------
__device__ __forceinline__ float fexp(float x) {
    float t = fmaxf(fminf(x * 1.4426950408889634f, 126.f), -126.f);
    float mg = t + 12582912.f;
    int   n  = __float_as_int(mg) - 0x4B400000;
    float f  = t - (mg - 12582912.f);
    float p  = 1.54035304e-4f;
    p = fmaf(p, f, 1.33335581e-3f);
    p = fmaf(p, f, 9.61812911e-3f);
    p = fmaf(p, f, 5.55041087e-2f);
    p = fmaf(p, f, 2.40226507e-1f);
    p = fmaf(p, f, 6.93147182e-1f);
    p = fmaf(p, f, 1.0f);
    return __int_as_float(__float_as_int(p) + (n << 23));
}

__device__ __forceinline__ void mma_f16f32(float& c0, float& c1, float& c2, float& c3,
                                           unsigned a0, unsigned a1, unsigned a2, unsigned a3,
                                           unsigned b0, unsigned b1)
{
    asm volatile(
        "mma.sync.aligned.m16n8k16.row.col.f32.f16.f16.f32 "
        "{%0,%1,%2,%3}, {%4,%5,%6,%7}, {%8,%9}, {%0,%1,%2,%3};"
        : "+f"(c0), "+f"(c1), "+f"(c2), "+f"(c3)
        : "r"(a0), "r"(a1), "r"(a2), "r"(a3), "r"(b0), "r"(b1));
}

__device__ __forceinline__ void ldsm_x4(unsigned& r0, unsigned& r1, unsigned& r2, unsigned& r3,
                                        unsigned addr)
{
    asm volatile("ldmatrix.sync.aligned.m8n8.x4.shared.b16 {%0,%1,%2,%3}, [%4];"
                 : "=r"(r0), "=r"(r1), "=r"(r2), "=r"(r3) : "r"(addr));
}

__device__ __forceinline__ void cp16(unsigned dst, const void* src) {
    asm volatile("cp.async.cg.shared.global [%0], [%1], 16;\n" :: "r"(dst), "l"(src));
}

// ---------------------------------------------------------------------------
// Generic f16-input / f32-accum NT GEMM. 128x128 block, 4 warps, warp 64x64,
// BK=64, 2-stage cp.async (64KB SMEM), ldmatrix.x4, 3 CTAs/SM.
// Batched via blockIdx.z with element strides sA/sB/sC (applied to C and Ch).
// ACT=0: r = alpha*(acc + bias); write C (f32) if non-null, Ch (f16) if non-null
// ACT=1: r = tanh(...); write C + Ch
// ACT=2: r = mask[z*T+col] ? 0 : exp(acc); write Ch; atomicAdd Z[r*B+z]
// ACT=3: r = acc * (1/Z[r*B+z]); write Ch
// ---------------------------------------------------------------------------
template <int ACT>
__global__ __launch_bounds__(128, 3)
void hgemm_nt(const __half* __restrict__ A, const __half* __restrict__ Bm,
              const float* __restrict__ bias, float* __restrict__ C,
              __half* __restrict__ Ch,
              const unsigned char* __restrict__ mk, float* __restrict__ Zb,
              int K, int lda, int ldb, int ldc,
              long sA, long sB, long sC, float alpha)
{
    extern __shared__ unsigned sh[];

    A  += (long)blockIdx.z * sA;
    Bm += (long)blockIdx.z * sB;
    if (C)  C  += (long)blockIdx.z * sC;
    if (Ch) Ch += (long)blockIdx.z * sC;
    if (ACT == 2) mk += (long)blockIdx.z * T_;

    const int t    = threadIdx.x;
    const int lane = t & 31;
    const int warp = t >> 5;
    const int wm   = (warp >> 1) * 64;
    const int wn   = (warp & 1) * 64;
    const int grp  = lane >> 2;
    const int qid  = lane & 3;

    const long m0 = (long)blockIdx.y * 128;
    const long n0 = (long)blockIdx.x * 128;

    float acc[4][8][4];
#pragma unroll
    for (int mi = 0; mi < 4; mi++)
#pragma unroll
        for (int ni = 0; ni < 8; ni++)
#pragma unroll
            for (int c = 0; c < 4; c++) acc[mi][ni][c] = 0.f;

    const int row0 = t >> 3;
    const int c8   = t & 7;
    const __half* aptr0 = A  + (m0 + row0) * lda + c8 * 8;
    const __half* bptr0 = Bm + (n0 + row0) * ldb + c8 * 8;
    const unsigned soff0 = (unsigned)(row0 * 128 + ((c8 ^ (row0 & 7)) << 4));
    const unsigned sbase = (unsigned)__cvta_generic_to_shared(sh);

    const int a_lr = lane & 15;
    const int a_cs = lane >> 4;
    unsigned a_off[4]; int a_m7[4];
#pragma unroll
    for (int mi = 0; mi < 4; mi++) {
        int m = wm + mi * 16 + a_lr;
        a_off[mi] = (unsigned)(m * 128);
        a_m7[mi]  = m & 7;
    }
    const int b_g  = lane >> 3;
    const int b_cs = b_g & 1;
    unsigned b_off[4]; int b_n7[4];
#pragma unroll
    for (int p = 0; p < 4; p++) {
        int n = wn + p * 16 + ((b_g & 2) << 2) + (lane & 7);
        b_off[p] = (unsigned)(n * 128);
        b_n7[p]  = n & 7;
    }

    auto issue = [&](int stage, int koff) {
        unsigned ab = sbase + (unsigned)stage * 32768u + soff0;
        unsigned bb = ab + 16384u;
#pragma unroll
        for (int i = 0; i < 8; i++) {
            cp16(ab + i * 2048u, aptr0 + (long)i * 16 * lda + koff);
            cp16(bb + i * 2048u, bptr0 + (long)i * 16 * ldb + koff);
        }
        asm volatile("cp.async.commit_group;\n" ::: "memory");
    };

    const int nIter = K >> 6;
    issue(0, 0);
    for (int it = 0; it < nIter; ++it) {
        asm volatile("cp.async.wait_group 0;\n" ::: "memory");
        __syncthreads();
        if (it + 1 < nIter) issue((it + 1) & 1, (it + 1) * 64);

        unsigned abase = sbase + (unsigned)(it & 1) * 32768u;
        unsigned bbase = abase + 16384u;
#pragma unroll
        for (int kk = 0; kk < 4; kk++) {
            unsigned af[4][4], bf[8][2];
            int ca = kk * 2 + a_cs;
            int cb = kk * 2 + b_cs;
#pragma unroll
            for (int mi = 0; mi < 4; mi++) {
                unsigned addr = abase + a_off[mi] + (unsigned)((ca ^ a_m7[mi]) << 4);
                ldsm_x4(af[mi][0], af[mi][1], af[mi][2], af[mi][3], addr);
            }
#pragma unroll
            for (int p = 0; p < 4; p++) {
                unsigned addr = bbase + b_off[p] + (unsigned)((cb ^ b_n7[p]) << 4);
                ldsm_x4(bf[2*p][0], bf[2*p][1], bf[2*p+1][0], bf[2*p+1][1], addr);
            }
#pragma unroll
            for (int mi = 0; mi < 4; mi++)
#pragma unroll
                for (int ni = 0; ni < 8; ni++)
                    mma_f16f32(acc[mi][ni][0], acc[mi][ni][1], acc[mi][ni][2], acc[mi][ni][3],
                               af[mi][0], af[mi][1], af[mi][2], af[mi][3],
                               bf[ni][0], bf[ni][1]);
        }
    }

#pragma unroll
    for (int mi = 0; mi < 4; mi++) {
        long r0 = m0 + wm + mi * 16 + grp;
        long r1 = r0 + 8;
        float e0 = 0.f, e1 = 0.f;
        float iz0 = 1.f, iz1 = 1.f;
        if (ACT == 3) {
            iz0 = 1.f / Zb[r0 * B_ + blockIdx.z];
            iz1 = 1.f / Zb[r1 * B_ + blockIdx.z];
        }
#pragma unroll
        for (int ni = 0; ni < 8; ni++) {
            long col = n0 + wn + ni * 8 + qid * 2;
            float bv0 = 0.f, bv1 = 0.f;
            if (bias) { bv0 = bias[col]; bv1 = bias[col + 1]; }
            float v00 = (acc[mi][ni][0] + bv0) * alpha;
            float v01 = (acc[mi][ni][1] + bv1) * alpha;
            float v10 = (acc[mi][ni][2] + bv0) * alpha;
            float v11 = (acc[mi][ni][3] + bv1) * alpha;
            if (ACT == 1) { v00 = tanhf(v00); v01 = tanhf(v01); v10 = tanhf(v10); v11 = tanhf(v11); }
            if (ACT == 2) {
                v00 = mk[col]     ? 0.f : fexp(v00);
                v01 = mk[col + 1] ? 0.f : fexp(v01);
                v10 = mk[col]     ? 0.f : fexp(v10);
                v11 = mk[col + 1] ? 0.f : fexp(v11);
                e0 += v00 + v01;
                e1 += v10 + v11;
            }
            if (ACT == 3) { v00 *= iz0; v01 *= iz0; v10 *= iz1; v11 *= iz1; }
            if (C) {
                *(float2*)(C + r0 * ldc + col) = make_float2(v00, v01);
                *(float2*)(C + r1 * ldc + col) = make_float2(v10, v11);
            }
            if (Ch) {
                *(__half2*)(Ch + r0 * ldc + col) = __floats2half2_rn(v00, v01);
                *(__half2*)(Ch + r1 * ldc + col) = __floats2half2_rn(v10, v11);
            }
        }
        if (ACT == 2) {
            e0 += __shfl_xor_sync(0xFFFFFFFFu, e0, 1);
            e0 += __shfl_xor_sync(0xFFFFFFFFu, e0, 2);
            e1 += __shfl_xor_sync(0xFFFFFFFFu, e1, 1);
            e1 += __shfl_xor_sync(0xFFFFFFFFu, e1, 2);
            if (qid == 0) {
                atomicAdd(Zb + r0 * B_ + blockIdx.z, e0);
                atomicAdd(Zb + r1 * B_ + blockIdx.z, e1);
            }
        }
    }
}

// ---------------------------------------------------------------------------
// Vocab GEMM: f16 in / f32 accum, fused exp-rowsum epilogue. (128,3).
// ---------------------------------------------------------------------------
__global__ __launch_bounds__(128, 3)
void mma_f16_nt_kernel(const __half* __restrict__ A,
                       const __half* __restrict__ Bm,
                       const float* __restrict__ bias, float* __restrict__ C,
                       float* __restrict__ rowsum,
                       int K, int lda, int ldb, int ldc)
{
    extern __shared__ unsigned sh[];

    const int t    = threadIdx.x;
    const int lane = t & 31;
    const int warp = t >> 5;
    const int wm   = (warp >> 1) * 64;
    const int wn   = (warp & 1) * 64;
    const int grp  = lane >> 2;
    const int qid  = lane & 3;

    const long m0 = (long)blockIdx.y * 128;
    const long n0 = (long)blockIdx.x * 128;

    float acc[4][8][4];
#pragma unroll
    for (int mi = 0; mi < 4; mi++)
#pragma unroll
        for (int ni = 0; ni < 8; ni++)
#pragma unroll
            for (int c = 0; c < 4; c++) acc[mi][ni][c] = 0.f;

    const int row0 = t >> 3;
    const int c8   = t & 7;
    const __half* aptr0 = A  + (m0 + row0) * lda + c8 * 8;
    const __half* bptr0 = Bm + (n0 + row0) * ldb + c8 * 8;
    const unsigned soff0 = (unsigned)(row0 * 128 + ((c8 ^ (row0 & 7)) << 4));
    const unsigned sbase = (unsigned)__cvta_generic_to_shared(sh);

    const int a_lr = lane & 15;
    const int a_cs = lane >> 4;
    unsigned a_off[4]; int a_m7[4];
#pragma unroll
    for (int mi = 0; mi < 4; mi++) {
        int m = wm + mi * 16 + a_lr;
        a_off[mi] = (unsigned)(m * 128);
        a_m7[mi]  = m & 7;
    }
    const int b_g  = lane >> 3;
    const int b_cs = b_g & 1;
    unsigned b_off[4]; int b_n7[4];
#pragma unroll
    for (int p = 0; p < 4; p++) {
        int n = wn + p * 16 + ((b_g & 2) << 2) + (lane & 7);
        b_off[p] = (unsigned)(n * 128);
        b_n7[p]  = n & 7;
    }

    auto issue = [&](int stage, int koff) {
        unsigned ab = sbase + (unsigned)stage * 32768u + soff0;
        unsigned bb = ab + 16384u;
#pragma unroll
        for (int i = 0; i < 8; i++) {
            cp16(ab + i * 2048u, aptr0 + (long)i * 16 * lda + koff);
            cp16(bb + i * 2048u, bptr0 + (long)i * 16 * ldb + koff);
        }
        asm volatile("cp.async.commit_group;\n" ::: "memory");
    };

    const int nIter = K >> 6;
    issue(0, 0);
    for (int it = 0; it < nIter; ++it) {
        asm volatile("cp.async.wait_group 0;\n" ::: "memory");
        __syncthreads();
        if (it + 1 < nIter) issue((it + 1) & 1, (it + 1) * 64);

        unsigned abase = sbase + (unsigned)(it & 1) * 32768u;
        unsigned bbase = abase + 16384u;
#pragma unroll
        for (int kk = 0; kk < 4; kk++) {
            unsigned af[4][4], bf[8][2];
            int ca = kk * 2 + a_cs;
            int cb = kk * 2 + b_cs;
#pragma unroll
            for (int mi = 0; mi < 4; mi++) {
                unsigned addr = abase + a_off[mi] + (unsigned)((ca ^ a_m7[mi]) << 4);
                ldsm_x4(af[mi][0], af[mi][1], af[mi][2], af[mi][3], addr);
            }
#pragma unroll
            for (int p = 0; p < 4; p++) {
                unsigned addr = bbase + b_off[p] + (unsigned)((cb ^ b_n7[p]) << 4);
                ldsm_x4(bf[2*p][0], bf[2*p][1], bf[2*p+1][0], bf[2*p+1][1], addr);
            }
#pragma unroll
            for (int mi = 0; mi < 4; mi++)
#pragma unroll
                for (int ni = 0; ni < 8; ni++)
                    mma_f16f32(acc[mi][ni][0], acc[mi][ni][1], acc[mi][ni][2], acc[mi][ni][3],
                               af[mi][0], af[mi][1], af[mi][2], af[mi][3],
                               bf[ni][0], bf[ni][1]);
        }
    }

#pragma unroll
    for (int mi = 0; mi < 4; mi++) {
        long r0 = m0 + wm + mi * 16 + grp;
        long r1 = r0 + 8;
        float e0 = 0.f, e1 = 0.f;
#pragma unroll
        for (int ni = 0; ni < 8; ni++) {
            long col = n0 + wn + ni * 8 + qid * 2;
            float bv0 = bias[col], bv1 = bias[col + 1];
            float v00 = acc[mi][ni][0] + bv0;
            float v01 = acc[mi][ni][1] + bv1;
            float v10 = acc[mi][ni][2] + bv0;
            float v11 = acc[mi][ni][3] + bv1;
            *(float2*)(C + r0 * ldc + col) = make_float2(v00, v01);
            *(float2*)(C + r1 * ldc + col) = make_float2(v10, v11);
            e0 += fexp(v00) + fexp(v01);
            e1 += fexp(v10) + fexp(v11);
        }
        e0 += __shfl_xor_sync(0xFFFFFFFFu, e0, 1);
        e0 += __shfl_xor_sync(0xFFFFFFFFu, e0, 2);
        e1 += __shfl_xor_sync(0xFFFFFFFFu, e1, 1);
        e1 += __shfl_xor_sync(0xFFFFFFFFu, e1, 2);
        if (qid == 0) {
            atomicAdd(rowsum + r0, e0);
            atomicAdd(rowsum + r1, e1);
        }
    }
}

// ---------------------------------------------------------------------------
// fp32 -> f16 convert
// ---------------------------------------------------------------------------
__global__ __launch_bounds__(256)
void f2h_kernel(const float4* __restrict__ in, __half2* __restrict__ out, int n4)
{
    int i = blockIdx.x * 256 + threadIdx.x;
    if (i >= n4) return;
    float4 v = in[i];
    out[i * 2]     = __floats2half2_rn(v.x, v.y);
    out[i * 2 + 1] = __floats2half2_rn(v.z, v.w);
}

__global__ void zero_kernel(float* __restrict__ p)
{
    p[blockIdx.x * 256 + threadIdx.x] = 0.f;
}

// ---------------------------------------------------------------------------
// f16 v transpose: vt[b][d][t] = v[(t*B+b)*D + d].
// ---------------------------------------------------------------------------
__global__ __launch_bounds__(256)
void vt_h_kernel(const __half* __restrict__ v, __half* __restrict__ vt)
{
    __shared__ __half tile[32][34];
    int b  = blockIdx.z;
    int t0 = blockIdx.x * 32;
    int d0 = blockIdx.y * 32;
    int x  = threadIdx.x & 31;
    int y  = threadIdx.x >> 5;
#pragma unroll
    for (int j = 0; j < 32; j += 8)
        tile[y + j][x] = v[((long)(t0 + y + j) * B_ + b) * D_ + d0 + x];
    __syncthreads();
#pragma unroll
    for (int j = 0; j < 32; j += 8)
        vt[(long)b * D_ * T_ + (long)(d0 + y + j) * T_ + t0 + x] = tile[x][y + j];
}

// ---------------------------------------------------------------------------
// LayerNorm(outs + x) -> f16 out.
// ---------------------------------------------------------------------------
__global__ __launch_bounds__(256)
void ln_kernel(const float* __restrict__ outs, const float* __restrict__ x,
               const float* __restrict__ g, const float* __restrict__ bb,
               __half* __restrict__ out)
{
    int row = blockIdx.x;
    int t = threadIdx.x;
    const float* o  = outs + (long)row * D_;
    const float* xr = x    + (long)row * D_;
    __shared__ float red[256];

    float v0 = o[t] + xr[t];
    float v1 = o[t + 256] + xr[t + 256];

    red[t] = v0 + v1; __syncthreads();
    for (int s = 128; s > 0; s >>= 1) { if (t < s) red[t] += red[t + s]; __syncthreads(); }
    float mu = red[0] * (1.f / D_); __syncthreads();

    float d0 = v0 - mu, d1 = v1 - mu;
    red[t] = d0 * d0 + d1 * d1; __syncthreads();
    for (int s = 128; s > 0; s >>= 1) { if (t < s) red[t] += red[t + s]; __syncthreads(); }
    float inv = rsqrtf(red[0] * (1.f / D_) + 1e-5f);

    out[(long)row * D_ + t]       = __float2half(d0 * inv * g[t]       + bb[t]);
    out[(long)row * D_ + t + 256] = __float2half(d1 * inv * g[t + 256] + bb[t + 256]);
}

// ---------------------------------------------------------------------------
// 2-way gate
// ---------------------------------------------------------------------------
__global__ __launch_bounds__(128)
void gates_kernel(const float* __restrict__ tok, const float* __restrict__ Wdiv,
                  const float* __restrict__ bdiv, float* __restrict__ gates)
{
    int row = blockIdx.x;
    int t = threadIdx.x;
    const float* x = tok + (long)row * D_;
    float z0 = 0.f, z1 = 0.f;
    for (int d = t; d < D_; d += 128) {
        float xv = x[d];
        z0 = fmaf(xv, Wdiv[d],      z0);
        z1 = fmaf(xv, Wdiv[D_ + d], z1);
    }
    __shared__ float r0[128], r1[128];
    r0[t] = z0; r1[t] = z1; __syncthreads();
    for (int s = 64; s > 0; s >>= 1) {
        if (t < s) { r0[t] += r0[t + s]; r1[t] += r1[t + s]; }
        __syncthreads();
    }
    if (t == 0) {
        float a = r0[0] + bdiv[0], b = r1[0] + bdiv[1];
        float m = fmaxf(a, b);
        float e0 = __expf(a - m), e1 = __expf(b - m);
        float inv = 1.f / (e0 + e1);
        gates[row * 2 + 0] = e0 * inv;
        gates[row * 2 + 1] = e1 * inv;
    }
}

// ---------------------------------------------------------------------------
// Fused coef + log-prob base + copy-scatter. One block (256 thr) per row.
// attn_h holds UNNORMALIZED exp(scores) in f16; zsum holds per-row Z.
// ---------------------------------------------------------------------------
__global__ __launch_bounds__(256)
void lp_scatter_kernel(float* __restrict__ out, const float* __restrict__ rowsum,
                       const float* __restrict__ gates, const __half* __restrict__ attn,
                       const float* __restrict__ zsum, const int* __restrict__ copy_seq)
{
    int row = blockIdx.x;
    int t   = threadIdx.x;
    int b   = row & (B_ - 1);

    float coef = __logf(gates[row * 2 + 0]) - __logf(rowsum[row]);
    float gate1z = gates[row * 2 + 1] / zsum[row];

    float4* o4 = (float4*)(out + (long)row * V_);
    for (int j = t; j < V_ / 4; j += 256) {
        float4 v = o4[j];
        v.x += coef; v.y += coef; v.z += coef; v.w += coef;
        o4[j] = v;
    }
    __syncthreads();

    const __half* arow = attn + (long)row * T_;
    float* orow = out + (long)row * V_;
#pragma unroll
    for (int e = 0; e < 4; e++) {
        int tt = t + e * 256;
        float val = gate1z * __half2float(arow[tt]);
        int idx = copy_seq[tt * B_ + b];
        int* ia = (int*)(orow + idx);
        int assumed = *ia;
        int old;
        do {
            old = assumed;
            float cur = __int_as_float(old);
            float nv = __logf(__expf(cur) + val);
            assumed = atomicCAS(ia, old, __float_as_int(nv));
        } while (assumed != old);
    }
}

// ---------------------------------------------------------------------------
// Launch
// ---------------------------------------------------------------------------
extern "C" void kernel_launch(void* const* d_in, const int* in_sizes, int n_in,
                              void* d_out, int out_size)
{
    const float* outs = (const float*)d_in[0];
    const float* gs   = (const float*)d_in[1];
    const unsigned char* mask = (const unsigned char*)d_in[2];
    const int*   cseq = (const int*)d_in[3];
    const float* Wq = (const float*)d_in[4],  *bq = (const float*)d_in[5];
    const float* Wk = (const float*)d_in[6],  *bk = (const float*)d_in[7];
    const float* Wv = (const float*)d_in[8],  *bv = (const float*)d_in[9];
    const float* Wo = (const float*)d_in[10], *bo = (const float*)d_in[11];
    const float* lng = (const float*)d_in[12], *lnb = (const float*)d_in[13];
    const float* Wt = (const float*)d_in[14], *bt = (const float*)d_in[15];
    const float* Wgen = (const float*)d_in[16], *bgen = (const float*)d_in[17];
    const float* Wdiv = (const float*)d_in[18], *bdiv = (const float*)d_in[19];
    float* out = (float*)d_out;

    float* sc = nullptr;
    cudaGetSymbolAddress((void**)&sc, g_scratch);
    float* x      = sc + OX;
    float* tok    = sc + OTOK;
    float* gts    = sc + OG;
    float* rowsum = sc + ORS;   // rowsum (SB) + zattn (SB) contiguous
    float* zattn  = sc + OZ;
    __half* outs_h = (__half*)(sc + OOH);
    __half* gs_h   = (__half*)(sc + OGH);
    __half* wq_h   = (__half*)(sc + OWQ);
    __half* wk_h   = (__half*)(sc + OWK);
    __half* wv_h   = (__half*)(sc + OWV);
    __half* wo_h   = (__half*)(sc + OWO);
    __half* wt_h   = (__half*)(sc + OWT);
    __half* q_h    = (__half*)(sc + OQH);
    __half* k_h    = (__half*)(sc + OKH);
    __half* v_h    = (__half*)(sc + OVH);
    __half* vt_h   = (__half*)(sc + OVT);
    __half* attn_h = (__half*)(sc + OAH);
    __half* ctx_h  = (__half*)(sc + OCH);
    __half* ln_h   = (__half*)(sc + OLH);
    __half* tok_h  = (__half*)(sc + OTH);
    __half* wgen_h = (__half*)(sc + OWG);

    const float scale = 0.044194173824159216f; // 1/sqrt(512)
    constexpr int SMEM = 65536;
    cudaFuncSetAttribute(hgemm_nt<0>, cudaFuncAttributeMaxDynamicSharedMemorySize, SMEM);
    cudaFuncSetAttribute(hgemm_nt<1>, cudaFuncAttributeMaxDynamicSharedMemorySize, SMEM);
    cudaFuncSetAttribute(hgemm_nt<2>, cudaFuncAttributeMaxDynamicSharedMemorySize, SMEM);
    cudaFuncSetAttribute(hgemm_nt<3>, cudaFuncAttributeMaxDynamicSharedMemorySize, SMEM);
    cudaFuncSetAttribute(mma_f16_nt_kernel, cudaFuncAttributeMaxDynamicSharedMemorySize, SMEM);
    dim3 blk(256);
    dim3 blkG(128);

    static cudaStream_t s2 = [] { cudaStream_t s; cudaStreamCreate(&s); return s; }();
    static cudaStream_t s3 = [] { cudaStream_t s; cudaStreamCreate(&s); return s; }();
    static cudaEvent_t evFork = [] { cudaEvent_t e; cudaEventCreateWithFlags(&e, cudaEventDisableTiming); return e; }();
    static cudaEvent_t evWgen = [] { cudaEvent_t e; cudaEventCreateWithFlags(&e, cudaEventDisableTiming); return e; }();
    static cudaEvent_t evCvt  = [] { cudaEvent_t e; cudaEventCreateWithFlags(&e, cudaEventDisableTiming); return e; }();
    static cudaEvent_t evQ    = [] { cudaEvent_t e; cudaEventCreateWithFlags(&e, cudaEventDisableTiming); return e; }();
    static cudaEvent_t evV    = [] { cudaEvent_t e; cudaEventCreateWithFlags(&e, cudaEventDisableTiming); return e; }();
    static cudaEvent_t evVT   = [] { cudaEvent_t e; cudaEventCreateWithFlags(&e, cudaEventDisableTiming); return e; }();
    static cudaEvent_t evG0   = [] { cudaEvent_t e; cudaEventCreateWithFlags(&e, cudaEventDisableTiming); return e; }();
    static cudaEvent_t evG1   = [] { cudaEvent_t e; cudaEventCreateWithFlags(&e, cudaEventDisableTiming); return e; }();
    static cudaEvent_t evG2   = [] { cudaEvent_t e; cudaEventCreateWithFlags(&e, cudaEventDisableTiming); return e; }();
    static cudaEvent_t evS0   = [] { cudaEvent_t e; cudaEventCreateWithFlags(&e, cudaEventDisableTiming); return e; }();

    // fork
    cudaEventRecord(evFork, 0);
    cudaStreamWaitEvent(s2, evFork, 0);
    cudaStreamWaitEvent(s3, evFork, 0);

    // s2: Wgen->f16 + zero(rowsum & zattn)
    f2h_kernel<<<(V_ * TS_ / 4 + 255) / 256, blk, 0, s2>>>((const float4*)Wgen, (__half2*)wgen_h, V_ * TS_ / 4);
    zero_kernel<<<2 * SB / 256, blk, 0, s2>>>(rowsum);
    cudaEventRecord(evWgen, s2);

    // s3: convert outs + all small weights
    f2h_kernel<<<(SB * D_ / 4 + 255) / 256, blk, 0, s3>>>((const float4*)outs, (__half2*)outs_h, SB * D_ / 4);
    f2h_kernel<<<(D_ * D_ / 4 + 255) / 256, blk, 0, s3>>>((const float4*)Wq, (__half2*)wq_h, D_ * D_ / 4);
    f2h_kernel<<<(D_ * D_ / 4 + 255) / 256, blk, 0, s3>>>((const float4*)Wk, (__half2*)wk_h, D_ * D_ / 4);
    f2h_kernel<<<(D_ * D_ / 4 + 255) / 256, blk, 0, s3>>>((const float4*)Wv, (__half2*)wv_h, D_ * D_ / 4);
    f2h_kernel<<<(D_ * D_ / 4 + 255) / 256, blk, 0, s3>>>((const float4*)Wo, (__half2*)wo_h, D_ * D_ / 4);
    f2h_kernel<<<(D_ * D_ / 4 + 255) / 256, blk, 0, s3>>>((const float4*)Wt, (__half2*)wt_h, D_ * D_ / 4);
    cudaEventRecord(evCvt, s3);

    // main: convert gs
    f2h_kernel<<<(TB * D_ / 4 + 255) / 256, blk>>>((const float4*)gs, (__half2*)gs_h, TB * D_ / 4);

    // main: join weight conversions, then k and v GEMMs (f16 out)
    cudaStreamWaitEvent(0, evCvt, 0);
    hgemm_nt<0><<<dim3(4, 64, 1), blkG, SMEM>>>(gs_h, wk_h, bk, nullptr, k_h, nullptr, nullptr,
                                                D_, D_, D_, D_, 0, 0, 0, 1.f);
    hgemm_nt<0><<<dim3(4, 64, 1), blkG, SMEM>>>(gs_h, wv_h, bv, nullptr, v_h, nullptr, nullptr,
                                                D_, D_, D_, D_, 0, 0, 0, 1.f);
    cudaEventRecord(evV, 0);

    // s3: q GEMM (f16 out) — needs only s3-resident conversions
    hgemm_nt<0><<<dim3(4, 16, 1), blkG, SMEM, s3>>>(outs_h, wq_h, bq, nullptr, q_h, nullptr, nullptr,
                                                    D_, D_, D_, D_, 0, 0, 0, scale);
    cudaEventRecord(evQ, s3);

    // s3: v transpose (f16) after v
    cudaStreamWaitEvent(s3, evV, 0);
    vt_h_kernel<<<dim3(32, 16, 8), blk, 0, s3>>>(v_h, vt_h);
    cudaEventRecord(evVT, s3);

    // main: join q + zeroed Z, then scores with fused exp+Z (attn_h f16)
    cudaStreamWaitEvent(0, evQ, 0);
    cudaStreamWaitEvent(0, evWgen, 0);
    hgemm_nt<2><<<dim3(8, 2, 8), blkG, SMEM>>>(q_h, k_h, nullptr, nullptr, attn_h, mask, zattn,
                                               D_, B_ * D_, B_ * D_, B_ * T_,
                                               D_, D_, T_, 1.f);

    // join vt, then ctx = (expS @ v)/Z -> ctx_h
    cudaStreamWaitEvent(0, evVT, 0);
    hgemm_nt<3><<<dim3(4, 2, 8), blkG, SMEM>>>(attn_h, vt_h, nullptr, nullptr, ctx_h, nullptr, zattn,
                                               T_, B_ * T_, T_, B_ * D_,
                                               T_, (long)D_ * T_, D_, 1.f);
    // x = ctx @ Wo^T + bo (f32)
    hgemm_nt<0><<<dim3(4, 16, 1), blkG, SMEM>>>(ctx_h, wo_h, bo, x, nullptr, nullptr, nullptr,
                                                D_, D_, D_, D_, 0, 0, 0, 1.f);
    // outs_ln = LN(outs + x) -> f16
    ln_kernel<<<SB, 256>>>(outs, x, lng, lnb, ln_h);
    // tok = tanh(ln @ Wt^T + bt) -> tok f32 + tok_h f16
    hgemm_nt<1><<<dim3(4, 16, 1), blkG, SMEM>>>(ln_h, wt_h, bt, tok, tok_h, nullptr, nullptr,
                                                D_, D_, D_, TS_, 0, 0, 0, 1.f);
    // gates
    gates_kernel<<<SB, 128>>>(tok, Wdiv, bdiv, gts);

    // vocab GEMM in 4 M-quarters, pipelined with lp_scatter
    constexpr int MQ = SB / 4;
    cudaEvent_t evG[3] = {evG0, evG1, evG2};
    for (int qi = 0; qi < 4; qi++) {
        long ro = (long)qi * MQ;
        mma_f16_nt_kernel<<<dim3(250, MQ / 128, 1), blkG, SMEM>>>(
            tok_h + ro * TS_, wgen_h, bgen, out + ro * V_, rowsum + ro,
            TS_, TS_, TS_, V_);
        if (qi < 3) cudaEventRecord(evG[qi], 0);
    }
    for (int qi = 0; qi < 3; qi++) {
        long ro = (long)qi * MQ;
        cudaStreamWaitEvent(s2, evG[qi], 0);
        lp_scatter_kernel<<<MQ, 256, 0, s2>>>(out + ro * V_, rowsum + ro, gts + 2 * ro,
                                              attn_h + ro * T_, zattn + ro, cseq);
    }
    cudaEventRecord(evS0, s2);
    {
        long ro = 3L * MQ;
        lp_scatter_kernel<<<MQ, 256>>>(out + ro * V_, rowsum + ro, gts + 2 * ro,
                                       attn_h + ro * T_, zattn + ro, cseq);
    }
    cudaStreamWaitEvent(0, evS0, 0);
}

// round 17
// speedup vs baseline: 1.1325x; 1.0487x over previous
#include <cuda_runtime.h>
#include <cuda_fp16.h>
#include <math.h>
#include <stdint.h>

// Problem dims (fixed for this dataset)
constexpr int S_  = 256;
constexpr int B_  = 8;
constexpr int T_  = 1024;
constexpr int D_  = 512;
constexpr int TS_ = 512;
constexpr int V_  = 32000;
constexpr int SB  = S_ * B_;   // 2048
constexpr int TB  = T_ * B_;   // 8192

// ---------------------------------------------------------------------------
// Scratch arena (f32 slots; __half buffers use half the slots)
// ---------------------------------------------------------------------------
constexpr size_t OX   = 0;                        // x (attn residual) f32 : SB*D
constexpr size_t OG   = OX   + (size_t)SB * D_;   // gates                : SB*2
constexpr size_t ORS  = OG   + (size_t)SB * 2;    // rowsum exp(logit)    : SB
constexpr size_t OZ   = ORS  + SB;                // attn Z               : SB
constexpr size_t OGA  = OZ   + SB;                // gate accum           : SB*2
constexpr size_t OBKV = OGA  + (size_t)SB * 2;    // packed bias kv       : 2*D
constexpr size_t OOH  = OBKV + 2 * D_;                   // outs_h  : SB*D/2
constexpr size_t OGH  = OOH  + (size_t)SB * D_ / 2;      // gs_h    : TB*D/2
constexpr size_t OWQ  = OGH  + (size_t)TB * D_ / 2;      // wq_h    : D*D/2
constexpr size_t OWKV = OWQ  + (size_t)D_ * D_ / 2;      // wkv_h   : D*D (1024x512 h)
constexpr size_t OWO  = OWKV + (size_t)D_ * D_;
constexpr size_t OWT  = OWO  + (size_t)D_ * D_ / 2;
constexpr size_t OQH  = OWT  + (size_t)D_ * D_ / 2;      // q_h     : SB*D/2
constexpr size_t OKV  = OQH  + (size_t)SB * D_ / 2;      // kv_h    : TB*1024 h = TB*D
constexpr size_t OVT  = OKV  + (size_t)TB * D_;          // vt_h    : TB*D/2
constexpr size_t OAH  = OVT  + (size_t)TB * D_ / 2;      // attn_h  : SB*T/2
constexpr size_t OCH  = OAH  + (size_t)SB * T_ / 2;      // ctx_h   : SB*D/2
constexpr size_t OLH  = OCH  + (size_t)SB * D_ / 2;      // ln_h    : SB*D/2
constexpr size_t OTH  = OLH  + (size_t)SB * D_ / 2;      // tok_h   : SB*TS/2
constexpr size_t OWG  = OTH  + (size_t)SB * TS_ / 2;     // wgen_h  : V*TS/2
constexpr size_t SCRATCH_FLOATS = OWG + (size_t)V_ * TS_ / 2;

__device__ float g_scratch[SCRATCH_FLOATS];

// ---------------------------------------------------------------------------
// math helpers
// ---------------------------------------------------------------------------
__device__ __forceinline__ float fexp(float x) {
    float t = fmaxf(fminf(x * 1.4426950408889634f, 126.f), -126.f);
    float mg = t + 12582912.f;
    int   n  = __float_as_int(mg) - 0x4B400000;
    float f  = t - (mg - 12582912.f);
    float p  = 1.54035304e-4f;
    p = fmaf(p, f, 1.33335581e-3f);
    p = fmaf(p, f, 9.61812911e-3f);
    p = fmaf(p, f, 5.55041087e-2f);
    p = fmaf(p, f, 2.40226507e-1f);
    p = fmaf(p, f, 6.93147182e-1f);
    p = fmaf(p, f, 1.0f);
    return __int_as_float(__float_as_int(p) + (n << 23));
}

__device__ __forceinline__ void mma_f16f32(float& c0, float& c1, float& c2, float& c3,
                                           unsigned a0, unsigned a1, unsigned a2, unsigned a3,
                                           unsigned b0, unsigned b1)
{
    asm volatile(
        "mma.sync.aligned.m16n8k16.row.col.f32.f16.f16.f32 "
        "{%0,%1,%2,%3}, {%4,%5,%6,%7}, {%8,%9}, {%0,%1,%2,%3};"
        : "+f"(c0), "+f"(c1), "+f"(c2), "+f"(c3)
        : "r"(a0), "r"(a1), "r"(a2), "r"(a3), "r"(b0), "r"(b1));
}

__device__ __forceinline__ void ldsm_x4(unsigned& r0, unsigned& r1, unsigned& r2, unsigned& r3,
                                        unsigned addr)
{
    asm volatile("ldmatrix.sync.aligned.m8n8.x4.shared.b16 {%0,%1,%2,%3}, [%4];"
                 : "=r"(r0), "=r"(r1), "=r"(r2), "=r"(r3) : "r"(addr));
}

__device__ __forceinline__ void cp16(unsigned dst, const void* src) {
    asm volatile("cp.async.cg.shared.global [%0], [%1], 16;\n" :: "r"(dst), "l"(src));
}

// ---------------------------------------------------------------------------
// Generic f16-input / f32-accum NT GEMM. 128x128 block, 4 warps, warp 64x64,
// BK=64, 2-stage cp.async (64KB SMEM), ldmatrix.x4, 3 CTAs/SM.
// ACT=0: r = alpha*(acc + bias); write C (f32) and/or Ch (f16)
// ACT=1: r = tanh(...); write C + Ch
// ACT=2: r = mask[z*T+col] ? 0 : exp(acc); write Ch; atomicAdd Z[r*B+z]
// ACT=3: r = acc * (1/Z[r*B+z]); write Ch
// ACT=4: r = tanh(acc + bias); write Ch; atomicAdd gate partials
//        gacc[r*2+j] += sum_col r*wdiv[j*ldc+col]
// ---------------------------------------------------------------------------
template <int ACT>
__global__ __launch_bounds__(128, 3)
void hgemm_nt(const __half* __restrict__ A, const __half* __restrict__ Bm,
              const float* __restrict__ bias, float* __restrict__ C,
              __half* __restrict__ Ch,
              const unsigned char* __restrict__ mk, float* __restrict__ Zb,
              const float* __restrict__ wdiv, float* __restrict__ gacc,
              int K, int lda, int ldb, int ldc,
              long sA, long sB, long sC, float alpha)
{
    extern __shared__ unsigned sh[];

    A  += (long)blockIdx.z * sA;
    Bm += (long)blockIdx.z * sB;
    if (C)  C  += (long)blockIdx.z * sC;
    if (Ch) Ch += (long)blockIdx.z * sC;
    if (ACT == 2) mk += (long)blockIdx.z * T_;

    const int t    = threadIdx.x;
    const int lane = t & 31;
    const int warp = t >> 5;
    const int wm   = (warp >> 1) * 64;
    const int wn   = (warp & 1) * 64;
    const int grp  = lane >> 2;
    const int qid  = lane & 3;

    const long m0 = (long)blockIdx.y * 128;
    const long n0 = (long)blockIdx.x * 128;

    float acc[4][8][4];
#pragma unroll
    for (int mi = 0; mi < 4; mi++)
#pragma unroll
        for (int ni = 0; ni < 8; ni++)
#pragma unroll
            for (int c = 0; c < 4; c++) acc[mi][ni][c] = 0.f;

    const int row0 = t >> 3;
    const int c8   = t & 7;
    const __half* aptr0 = A  + (m0 + row0) * lda + c8 * 8;
    const __half* bptr0 = Bm + (n0 + row0) * ldb + c8 * 8;
    const unsigned soff0 = (unsigned)(row0 * 128 + ((c8 ^ (row0 & 7)) << 4));
    const unsigned sbase = (unsigned)__cvta_generic_to_shared(sh);

    const int a_lr = lane & 15;
    const int a_cs = lane >> 4;
    unsigned a_off[4]; int a_m7[4];
#pragma unroll
    for (int mi = 0; mi < 4; mi++) {
        int m = wm + mi * 16 + a_lr;
        a_off[mi] = (unsigned)(m * 128);
        a_m7[mi]  = m & 7;
    }
    const int b_g  = lane >> 3;
    const int b_cs = b_g & 1;
    unsigned b_off[4]; int b_n7[4];
#pragma unroll
    for (int p = 0; p < 4; p++) {
        int n = wn + p * 16 + ((b_g & 2) << 2) + (lane & 7);
        b_off[p] = (unsigned)(n * 128);
        b_n7[p]  = n & 7;
    }

    auto issue = [&](int stage, int koff) {
        unsigned ab = sbase + (unsigned)stage * 32768u + soff0;
        unsigned bb = ab + 16384u;
#pragma unroll
        for (int i = 0; i < 8; i++) {
            cp16(ab + i * 2048u, aptr0 + (long)i * 16 * lda + koff);
            cp16(bb + i * 2048u, bptr0 + (long)i * 16 * ldb + koff);
        }
        asm volatile("cp.async.commit_group;\n" ::: "memory");
    };

    const int nIter = K >> 6;
    issue(0, 0);
    for (int it = 0; it < nIter; ++it) {
        asm volatile("cp.async.wait_group 0;\n" ::: "memory");
        __syncthreads();
        if (it + 1 < nIter) issue((it + 1) & 1, (it + 1) * 64);

        unsigned abase = sbase + (unsigned)(it & 1) * 32768u;
        unsigned bbase = abase + 16384u;
#pragma unroll
        for (int kk = 0; kk < 4; kk++) {
            unsigned af[4][4], bf[8][2];
            int ca = kk * 2 + a_cs;
            int cb = kk * 2 + b_cs;
#pragma unroll
            for (int mi = 0; mi < 4; mi++) {
                unsigned addr = abase + a_off[mi] + (unsigned)((ca ^ a_m7[mi]) << 4);
                ldsm_x4(af[mi][0], af[mi][1], af[mi][2], af[mi][3], addr);
            }
#pragma unroll
            for (int p = 0; p < 4; p++) {
                unsigned addr = bbase + b_off[p] + (unsigned)((cb ^ b_n7[p]) << 4);
                ldsm_x4(bf[2*p][0], bf[2*p][1], bf[2*p+1][0], bf[2*p+1][1], addr);
            }
#pragma unroll
            for (int mi = 0; mi < 4; mi++)
#pragma unroll
                for (int ni = 0; ni < 8; ni++)
                    mma_f16f32(acc[mi][ni][0], acc[mi][ni][1], acc[mi][ni][2], acc[mi][ni][3],
                               af[mi][0], af[mi][1], af[mi][2], af[mi][3],
                               bf[ni][0], bf[ni][1]);
        }
    }

#pragma unroll
    for (int mi = 0; mi < 4; mi++) {
        long r0 = m0 + wm + mi * 16 + grp;
        long r1 = r0 + 8;
        float e0 = 0.f, e1 = 0.f;            // ACT2 Z sums / unused
        float g00 = 0.f, g01 = 0.f, g10 = 0.f, g11 = 0.f;  // ACT4 gate partials
        float iz0 = 1.f, iz1 = 1.f;
        if (ACT == 3) {
            iz0 = 1.f / Zb[r0 * B_ + blockIdx.z];
            iz1 = 1.f / Zb[r1 * B_ + blockIdx.z];
        }
#pragma unroll
        for (int ni = 0; ni < 8; ni++) {
            long col = n0 + wn + ni * 8 + qid * 2;
            float bv0 = 0.f, bv1 = 0.f;
            if (bias) { bv0 = bias[col]; bv1 = bias[col + 1]; }
            float v00 = (acc[mi][ni][0] + bv0) * alpha;
            float v01 = (acc[mi][ni][1] + bv1) * alpha;
            float v10 = (acc[mi][ni][2] + bv0) * alpha;
            float v11 = (acc[mi][ni][3] + bv1) * alpha;
            if (ACT == 1 || ACT == 4) {
                v00 = tanhf(v00); v01 = tanhf(v01); v10 = tanhf(v10); v11 = tanhf(v11);
            }
            if (ACT == 2) {
                v00 = mk[col]     ? 0.f : fexp(v00);
                v01 = mk[col + 1] ? 0.f : fexp(v01);
                v10 = mk[col]     ? 0.f : fexp(v10);
                v11 = mk[col + 1] ? 0.f : fexp(v11);
                e0 += v00 + v01;
                e1 += v10 + v11;
            }
            if (ACT == 3) { v00 *= iz0; v01 *= iz0; v10 *= iz1; v11 *= iz1; }
            if (ACT == 4) {
                float w00 = wdiv[col], w01 = wdiv[col + 1];
                float w10 = wdiv[ldc + col], w11 = wdiv[ldc + col + 1];
                g00 = fmaf(v00, w00, fmaf(v01, w01, g00));
                g01 = fmaf(v00, w10, fmaf(v01, w11, g01));
                g10 = fmaf(v10, w00, fmaf(v11, w01, g10));
                g11 = fmaf(v10, w10, fmaf(v11, w11, g11));
            }
            if (C) {
                *(float2*)(C + r0 * ldc + col) = make_float2(v00, v01);
                *(float2*)(C + r1 * ldc + col) = make_float2(v10, v11);
            }
            if (Ch) {
                *(__half2*)(Ch + r0 * ldc + col) = __floats2half2_rn(v00, v01);
                *(__half2*)(Ch + r1 * ldc + col) = __floats2half2_rn(v10, v11);
            }
        }
        if (ACT == 2) {
            e0 += __shfl_xor_sync(0xFFFFFFFFu, e0, 1);
            e0 += __shfl_xor_sync(0xFFFFFFFFu, e0, 2);
            e1 += __shfl_xor_sync(0xFFFFFFFFu, e1, 1);
            e1 += __shfl_xor_sync(0xFFFFFFFFu, e1, 2);
            if (qid == 0) {
                atomicAdd(Zb + r0 * B_ + blockIdx.z, e0);
                atomicAdd(Zb + r1 * B_ + blockIdx.z, e1);
            }
        }
        if (ACT == 4) {
            g00 += __shfl_xor_sync(0xFFFFFFFFu, g00, 1);
            g00 += __shfl_xor_sync(0xFFFFFFFFu, g00, 2);
            g01 += __shfl_xor_sync(0xFFFFFFFFu, g01, 1);
            g01 += __shfl_xor_sync(0xFFFFFFFFu, g01, 2);
            g10 += __shfl_xor_sync(0xFFFFFFFFu, g10, 1);
            g10 += __shfl_xor_sync(0xFFFFFFFFu, g10, 2);
            g11 += __shfl_xor_sync(0xFFFFFFFFu, g11, 1);
            g11 += __shfl_xor_sync(0xFFFFFFFFu, g11, 2);
            if (qid == 0) {
                atomicAdd(gacc + r0 * 2,     g00);
                atomicAdd(gacc + r0 * 2 + 1, g01);
                atomicAdd(gacc + r1 * 2,     g10);
                atomicAdd(gacc + r1 * 2 + 1, g11);
            }
        }
    }
}

// ---------------------------------------------------------------------------
// Vocab GEMM: f16 in / f32 accum, fused exp-rowsum epilogue. (128,3).
// ---------------------------------------------------------------------------
__global__ __launch_bounds__(128, 3)
void mma_f16_nt_kernel(const __half* __restrict__ A,
                       const __half* __restrict__ Bm,
                       const float* __restrict__ bias, float* __restrict__ C,
                       float* __restrict__ rowsum,
                       int K, int lda, int ldb, int ldc)
{
    extern __shared__ unsigned sh[];

    const int t    = threadIdx.x;
    const int lane = t & 31;
    const int warp = t >> 5;
    const int wm   = (warp >> 1) * 64;
    const int wn   = (warp & 1) * 64;
    const int grp  = lane >> 2;
    const int qid  = lane & 3;

    const long m0 = (long)blockIdx.y * 128;
    const long n0 = (long)blockIdx.x * 128;

    float acc[4][8][4];
#pragma unroll
    for (int mi = 0; mi < 4; mi++)
#pragma unroll
        for (int ni = 0; ni < 8; ni++)
#pragma unroll
            for (int c = 0; c < 4; c++) acc[mi][ni][c] = 0.f;

    const int row0 = t >> 3;
    const int c8   = t & 7;
    const __half* aptr0 = A  + (m0 + row0) * lda + c8 * 8;
    const __half* bptr0 = Bm + (n0 + row0) * ldb + c8 * 8;
    const unsigned soff0 = (unsigned)(row0 * 128 + ((c8 ^ (row0 & 7)) << 4));
    const unsigned sbase = (unsigned)__cvta_generic_to_shared(sh);

    const int a_lr = lane & 15;
    const int a_cs = lane >> 4;
    unsigned a_off[4]; int a_m7[4];
#pragma unroll
    for (int mi = 0; mi < 4; mi++) {
        int m = wm + mi * 16 + a_lr;
        a_off[mi] = (unsigned)(m * 128);
        a_m7[mi]  = m & 7;
    }
    const int b_g  = lane >> 3;
    const int b_cs = b_g & 1;
    unsigned b_off[4]; int b_n7[4];
#pragma unroll
    for (int p = 0; p < 4; p++) {
        int n = wn + p * 16 + ((b_g & 2) << 2) + (lane & 7);
        b_off[p] = (unsigned)(n * 128);
        b_n7[p]  = n & 7;
    }

    auto issue = [&](int stage, int koff) {
        unsigned ab = sbase + (unsigned)stage * 32768u + soff0;
        unsigned bb = ab + 16384u;
#pragma unroll
        for (int i = 0; i < 8; i++) {
            cp16(ab + i * 2048u, aptr0 + (long)i * 16 * lda + koff);
            cp16(bb + i * 2048u, bptr0 + (long)i * 16 * ldb + koff);
        }
        asm volatile("cp.async.commit_group;\n" ::: "memory");
    };

    const int nIter = K >> 6;
    issue(0, 0);
    for (int it = 0; it < nIter; ++it) {
        asm volatile("cp.async.wait_group 0;\n" ::: "memory");
        __syncthreads();
        if (it + 1 < nIter) issue((it + 1) & 1, (it + 1) * 64);

        unsigned abase = sbase + (unsigned)(it & 1) * 32768u;
        unsigned bbase = abase + 16384u;
#pragma unroll
        for (int kk = 0; kk < 4; kk++) {
            unsigned af[4][4], bf[8][2];
            int ca = kk * 2 + a_cs;
            int cb = kk * 2 + b_cs;
#pragma unroll
            for (int mi = 0; mi < 4; mi++) {
                unsigned addr = abase + a_off[mi] + (unsigned)((ca ^ a_m7[mi]) << 4);
                ldsm_x4(af[mi][0], af[mi][1], af[mi][2], af[mi][3], addr);
            }
#pragma unroll
            for (int p = 0; p < 4; p++) {
                unsigned addr = bbase + b_off[p] + (unsigned)((cb ^ b_n7[p]) << 4);
                ldsm_x4(bf[2*p][0], bf[2*p][1], bf[2*p+1][0], bf[2*p+1][1], addr);
            }
#pragma unroll
            for (int mi = 0; mi < 4; mi++)
#pragma unroll
                for (int ni = 0; ni < 8; ni++)
                    mma_f16f32(acc[mi][ni][0], acc[mi][ni][1], acc[mi][ni][2], acc[mi][ni][3],
                               af[mi][0], af[mi][1], af[mi][2], af[mi][3],
                               bf[ni][0], bf[ni][1]);
        }
    }

#pragma unroll
    for (int mi = 0; mi < 4; mi++) {
        long r0 = m0 + wm + mi * 16 + grp;
        long r1 = r0 + 8;
        float e0 = 0.f, e1 = 0.f;
#pragma unroll
        for (int ni = 0; ni < 8; ni++) {
            long col = n0 + wn + ni * 8 + qid * 2;
            float bv0 = bias[col], bv1 = bias[col + 1];
            float v00 = acc[mi][ni][0] + bv0;
            float v01 = acc[mi][ni][1] + bv1;
            float v10 = acc[mi][ni][2] + bv0;
            float v11 = acc[mi][ni][3] + bv1;
            *(float2*)(C + r0 * ldc + col) = make_float2(v00, v01);
            *(float2*)(C + r1 * ldc + col) = make_float2(v10, v11);
            e0 += fexp(v00) + fexp(v01);
            e1 += fexp(v10) + fexp(v11);
        }
        e0 += __shfl_xor_sync(0xFFFFFFFFu, e0, 1);
        e0 += __shfl_xor_sync(0xFFFFFFFFu, e0, 2);
        e1 += __shfl_xor_sync(0xFFFFFFFFu, e1, 1);
        e1 += __shfl_xor_sync(0xFFFFFFFFu, e1, 2);
        if (qid == 0) {
            atomicAdd(rowsum + r0, e0);
            atomicAdd(rowsum + r1, e1);
        }
    }
}

// ---------------------------------------------------------------------------
// fp32 -> f16 convert / zero / bias pack
// ---------------------------------------------------------------------------
__global__ __launch_bounds__(256)
void f2h_kernel(const float4* __restrict__ in, __half2* __restrict__ out, int n4)
{
    int i = blockIdx.x * 256 + threadIdx.x;
    if (i >= n4) return;
    float4 v = in[i];
    out[i * 2]     = __floats2half2_rn(v.x, v.y);
    out[i * 2 + 1] = __floats2half2_rn(v.z, v.w);
}

__global__ void zero_kernel(float* __restrict__ p)
{
    p[blockIdx.x * 256 + threadIdx.x] = 0.f;
}

__global__ void pack_bkv_kernel(const float* __restrict__ bk, const float* __restrict__ bv,
                                float* __restrict__ bkv)
{
    int i = blockIdx.x * 256 + threadIdx.x;
    bkv[i] = (i < D_) ? bk[i] : bv[i - D_];
}

// gate finalize: softmax over the 2 accumulated gate logits (+bdiv)
__global__ void gfin_kernel(const float* __restrict__ gacc, const float* __restrict__ bdiv,
                            float* __restrict__ gates)
{
    int r = blockIdx.x * 256 + threadIdx.x;
    float a = gacc[r * 2 + 0] + bdiv[0];
    float b = gacc[r * 2 + 1] + bdiv[1];
    float m = fmaxf(a, b);
    float e0 = __expf(a - m), e1 = __expf(b - m);
    float inv = 1.f / (e0 + e1);
    gates[r * 2 + 0] = e0 * inv;
    gates[r * 2 + 1] = e1 * inv;
}

// ---------------------------------------------------------------------------
// f16 v transpose from kv buffer: vt[b][d][t] = kv[(t*B+b)*ldv + off + d].
// ---------------------------------------------------------------------------
__global__ __launch_bounds__(256)
void vt_h_kernel(const __half* __restrict__ v, __half* __restrict__ vt, int ldv)
{
    __shared__ __half tile[32][34];
    int b  = blockIdx.z;
    int t0 = blockIdx.x * 32;
    int d0 = blockIdx.y * 32;
    int x  = threadIdx.x & 31;
    int y  = threadIdx.x >> 5;
#pragma unroll
    for (int j = 0; j < 32; j += 8)
        tile[y + j][x] = v[((long)(t0 + y + j) * B_ + b) * ldv + d0 + x];
    __syncthreads();
#pragma unroll
    for (int j = 0; j < 32; j += 8)
        vt[(long)b * D_ * T_ + (long)(d0 + y + j) * T_ + t0 + x] = tile[x][y + j];
}

// ---------------------------------------------------------------------------
// LayerNorm(outs + x) -> f16 out.
// ---------------------------------------------------------------------------
__global__ __launch_bounds__(256)
void ln_kernel(const float* __restrict__ outs, const float* __restrict__ x,
               const float* __restrict__ g, const float* __restrict__ bb,
               __half* __restrict__ out)
{
    int row = blockIdx.x;
    int t = threadIdx.x;
    const float* o  = outs + (long)row * D_;
    const float* xr = x    + (long)row * D_;
    __shared__ float red[256];

    float v0 = o[t] + xr[t];
    float v1 = o[t + 256] + xr[t + 256];

    red[t] = v0 + v1; __syncthreads();
    for (int s = 128; s > 0; s >>= 1) { if (t < s) red[t] += red[t + s]; __syncthreads(); }
    float mu = red[0] * (1.f / D_); __syncthreads();

    float d0 = v0 - mu, d1 = v1 - mu;
    red[t] = d0 * d0 + d1 * d1; __syncthreads();
    for (int s = 128; s > 0; s >>= 1) { if (t < s) red[t] += red[t + s]; __syncthreads(); }
    float inv = rsqrtf(red[0] * (1.f / D_) + 1e-5f);

    out[(long)row * D_ + t]       = __float2half(d0 * inv * g[t]       + bb[t]);
    out[(long)row * D_ + t + 256] = __float2half(d1 * inv * g[t + 256] + bb[t + 256]);
}

// ---------------------------------------------------------------------------
// Fused coef + log-prob base + copy-scatter. One block (256 thr) per row.
// ---------------------------------------------------------------------------
__global__ __launch_bounds__(256)
void lp_scatter_kernel(float* __restrict__ out, const float* __restrict__ rowsum,
                       const float* __restrict__ gates, const __half* __restrict__ attn,
                       const float* __restrict__ zsum, const int* __restrict__ copy_seq)
{
    int row = blockIdx.x;
    int t   = threadIdx.x;
    int b   = row & (B_ - 1);

    float coef = __logf(gates[row * 2 + 0]) - __logf(rowsum[row]);
    float gate1z = gates[row * 2 + 1] / zsum[row];

    float4* o4 = (float4*)(out + (long)row * V_);
    for (int j = t; j < V_ / 4; j += 256) {
        float4 v = o4[j];
        v.x += coef; v.y += coef; v.z += coef; v.w += coef;
        o4[j] = v;
    }
    __syncthreads();

    const __half* arow = attn + (long)row * T_;
    float* orow = out + (long)row * V_;
#pragma unroll
    for (int e = 0; e < 4; e++) {
        int tt = t + e * 256;
        float val = gate1z * __half2float(arow[tt]);
        int idx = copy_seq[tt * B_ + b];
        int* ia = (int*)(orow + idx);
        int assumed = *ia;
        int old;
        do {
            old = assumed;
            float cur = __int_as_float(old);
            float nv = __logf(__expf(cur) + val);
            assumed = atomicCAS(ia, old, __float_as_int(nv));
        } while (assumed != old);
    }
}

// ---------------------------------------------------------------------------
// Launch
// ---------------------------------------------------------------------------
extern "C" void kernel_launch(void* const* d_in, const int* in_sizes, int n_in,
                              void* d_out, int out_size)
{
    const float* outs = (const float*)d_in[0];
    const float* gs   = (const float*)d_in[1];
    const unsigned char* mask = (const unsigned char*)d_in[2];
    const int*   cseq = (const int*)d_in[3];
    const float* Wq = (const float*)d_in[4],  *bq = (const float*)d_in[5];
    const float* Wk = (const float*)d_in[6],  *bk = (const float*)d_in[7];
    const float* Wv = (const float*)d_in[8],  *bv = (const float*)d_in[9];
    const float* Wo = (const float*)d_in[10], *bo = (const float*)d_in[11];
    const float* lng = (const float*)d_in[12], *lnb = (const float*)d_in[13];
    const float* Wt = (const float*)d_in[14], *bt = (const float*)d_in[15];
    const float* Wgen = (const float*)d_in[16], *bgen = (const float*)d_in[17];
    const float* Wdiv = (const float*)d_in[18], *bdiv = (const float*)d_in[19];
    float* out = (float*)d_out;

    float* sc = nullptr;
    cudaGetSymbolAddress((void**)&sc, g_scratch);
    float* x      = sc + OX;
    float* gts    = sc + OG;
    float* rowsum = sc + ORS;   // rowsum(SB) + zattn(SB) + gacc(2SB) contiguous
    float* zattn  = sc + OZ;
    float* gacc   = sc + OGA;
    float* bkv    = sc + OBKV;
    __half* outs_h = (__half*)(sc + OOH);
    __half* gs_h   = (__half*)(sc + OGH);
    __half* wq_h   = (__half*)(sc + OWQ);
    __half* wkv_h  = (__half*)(sc + OWKV);
    __half* wo_h   = (__half*)(sc + OWO);
    __half* wt_h   = (__half*)(sc + OWT);
    __half* q_h    = (__half*)(sc + OQH);
    __half* kv_h   = (__half*)(sc + OKV);
    __half* vt_h   = (__half*)(sc + OVT);
    __half* attn_h = (__half*)(sc + OAH);
    __half* ctx_h  = (__half*)(sc + OCH);
    __half* ln_h   = (__half*)(sc + OLH);
    __half* tok_h  = (__half*)(sc + OTH);
    __half* wgen_h = (__half*)(sc + OWG);

    const float scale = 0.044194173824159216f; // 1/sqrt(512)
    constexpr int SMEM = 65536;
    constexpr int KV_LD = 2 * D_;              // 1024
    cudaFuncSetAttribute(hgemm_nt<0>, cudaFuncAttributeMaxDynamicSharedMemorySize, SMEM);
    cudaFuncSetAttribute(hgemm_nt<2>, cudaFuncAttributeMaxDynamicSharedMemorySize, SMEM);
    cudaFuncSetAttribute(hgemm_nt<3>, cudaFuncAttributeMaxDynamicSharedMemorySize, SMEM);
    cudaFuncSetAttribute(hgemm_nt<4>, cudaFuncAttributeMaxDynamicSharedMemorySize, SMEM);
    cudaFuncSetAttribute(mma_f16_nt_kernel, cudaFuncAttributeMaxDynamicSharedMemorySize, SMEM);
    dim3 blk(256);
    dim3 blkG(128);

    static cudaStream_t s2 = [] { cudaStream_t s; cudaStreamCreate(&s); return s; }();
    static cudaStream_t s3 = [] { cudaStream_t s; cudaStreamCreate(&s); return s; }();
    static cudaEvent_t evFork = [] { cudaEvent_t e; cudaEventCreateWithFlags(&e, cudaEventDisableTiming); return e; }();
    static cudaEvent_t evWgen = [] { cudaEvent_t e; cudaEventCreateWithFlags(&e, cudaEventDisableTiming); return e; }();
    static cudaEvent_t evCvt  = [] { cudaEvent_t e; cudaEventCreateWithFlags(&e, cudaEventDisableTiming); return e; }();
    static cudaEvent_t evQ    = [] { cudaEvent_t e; cudaEventCreateWithFlags(&e, cudaEventDisableTiming); return e; }();
    static cudaEvent_t evV    = [] { cudaEvent_t e; cudaEventCreateWithFlags(&e, cudaEventDisableTiming); return e; }();
    static cudaEvent_t evVT   = [] { cudaEvent_t e; cudaEventCreateWithFlags(&e, cudaEventDisableTiming); return e; }();
    static cudaEvent_t evG0   = [] { cudaEvent_t e; cudaEventCreateWithFlags(&e, cudaEventDisableTiming); return e; }();
    static cudaEvent_t evG1   = [] { cudaEvent_t e; cudaEventCreateWithFlags(&e, cudaEventDisableTiming); return e; }();
    static cudaEvent_t evG2   = [] { cudaEvent_t e; cudaEventCreateWithFlags(&e, cudaEventDisableTiming); return e; }();
    static cudaEvent_t evS0   = [] { cudaEvent_t e; cudaEventCreateWithFlags(&e, cudaEventDisableTiming); return e; }();

    // fork
    cudaEventRecord(evFork, 0);
    cudaStreamWaitEvent(s2, evFork, 0);
    cudaStreamWaitEvent(s3, evFork, 0);

    // s2: Wgen->f16 + zero(rowsum, zattn, gacc)
    f2h_kernel<<<(V_ * TS_ / 4 + 255) / 256, blk, 0, s2>>>((const float4*)Wgen, (__half2*)wgen_h, V_ * TS_ / 4);
    zero_kernel<<<4 * SB / 256, blk, 0, s2>>>(rowsum);
    cudaEventRecord(evWgen, s2);

    // s3: convert outs + q/o/t weights, then q GEMM
    f2h_kernel<<<(SB * D_ / 4 + 255) / 256, blk, 0, s3>>>((const float4*)outs, (__half2*)outs_h, SB * D_ / 4);
    f2h_kernel<<<(D_ * D_ / 4 + 255) / 256, blk, 0, s3>>>((const float4*)Wq, (__half2*)wq_h, D_ * D_ / 4);
    f2h_kernel<<<(D_ * D_ / 4 + 255) / 256, blk, 0, s3>>>((const float4*)Wo, (__half2*)wo_h, D_ * D_ / 4);
    f2h_kernel<<<(D_ * D_ / 4 + 255) / 256, blk, 0, s3>>>((const float4*)Wt, (__half2*)wt_h, D_ * D_ / 4);
    hgemm_nt<0><<<dim3(4, 16, 1), blkG, SMEM, s3>>>(outs_h, wq_h, bq, nullptr, q_h, nullptr, nullptr,
                                                    nullptr, nullptr, D_, D_, D_, D_, 0, 0, 0, scale);
    cudaEventRecord(evQ, s3);

    // main: convert gs + packed Wk|Wv + bias pack
    f2h_kernel<<<(TB * D_ / 4 + 255) / 256, blk>>>((const float4*)gs, (__half2*)gs_h, TB * D_ / 4);
    f2h_kernel<<<(D_ * D_ / 4 + 255) / 256, blk>>>((const float4*)Wk, (__half2*)wkv_h, D_ * D_ / 4);
    f2h_kernel<<<(D_ * D_ / 4 + 255) / 256, blk>>>((const float4*)Wv, (__half2*)(wkv_h + (size_t)D_ * D_), D_ * D_ / 4);
    pack_bkv_kernel<<<KV_LD / 256, blk>>>(bk, bv, bkv);

    // main: fused k|v GEMM -> kv_h [TB x 1024] (k cols 0..511, v cols 512..1023)
    hgemm_nt<0><<<dim3(8, 64, 1), blkG, SMEM>>>(gs_h, wkv_h, bkv, nullptr, kv_h, nullptr, nullptr,
                                                nullptr, nullptr, D_, D_, D_, KV_LD, 0, 0, 0, 1.f);
    cudaEventRecord(evV, 0);

    // s3: v transpose from kv buffer (after kv GEMM)
    cudaStreamWaitEvent(s3, evV, 0);
    vt_h_kernel<<<dim3(32, 16, 8), blk, 0, s3>>>(kv_h + D_, vt_h, KV_LD);
    cudaEventRecord(evVT, s3);

    // main: join q + zeroed Z, then scores with fused exp+Z
    cudaStreamWaitEvent(0, evQ, 0);
    cudaStreamWaitEvent(0, evWgen, 0);
    hgemm_nt<2><<<dim3(8, 2, 8), blkG, SMEM>>>(q_h, kv_h, nullptr, nullptr, attn_h, mask, zattn,
                                               nullptr, nullptr,
                                               D_, B_ * D_, B_ * KV_LD, B_ * T_,
                                               D_, KV_LD, T_, 1.f);

    // join vt, then ctx = (expS @ v)/Z -> ctx_h
    cudaStreamWaitEvent(0, evVT, 0);
    hgemm_nt<3><<<dim3(4, 2, 8), blkG, SMEM>>>(attn_h, vt_h, nullptr, nullptr, ctx_h, nullptr, zattn,
                                               nullptr, nullptr,
                                               T_, B_ * T_, T_, B_ * D_,
                                               T_, (long)D_ * T_, D_, 1.f);
    // x = ctx @ Wo^T + bo (f32)
    hgemm_nt<0><<<dim3(4, 16, 1), blkG, SMEM>>>(ctx_h, wo_h, bo, x, nullptr, nullptr, nullptr,
                                                nullptr, nullptr, D_, D_, D_, D_, 0, 0, 0, 1.f);
    // outs_ln = LN(outs + x) -> f16
    ln_kernel<<<SB, 256>>>(outs, x, lng, lnb, ln_h);
    // tok = tanh(ln @ Wt^T + bt) -> tok_h + fused gate partials
    hgemm_nt<4><<<dim3(4, 16, 1), blkG, SMEM>>>(ln_h, wt_h, bt, nullptr, tok_h, nullptr, nullptr,
                                                Wdiv, gacc, D_, D_, D_, TS_, 0, 0, 0, 1.f);
    // gate finalize
    gfin_kernel<<<SB / 256, blk>>>(gacc, bdiv, gts);

    // vocab GEMM in 4 M-quarters, pipelined with lp_scatter
    constexpr int MQ = SB / 4;
    cudaEvent_t evG[3] = {evG0, evG1, evG2};
    for (int qi = 0; qi < 4; qi++) {
        long ro = (long)qi * MQ;
        mma_f16_nt_kernel<<<dim3(250, MQ / 128, 1), blkG, SMEM>>>(
            tok_h + ro * TS_, wgen_h, bgen, out + ro * V_, rowsum + ro,
            TS_, TS_, TS_, V_);
        if (qi < 3) cudaEventRecord(evG[qi], 0);
    }
    for (int qi = 0; qi < 3; qi++) {
        long ro = (long)qi * MQ;
        cudaStreamWaitEvent(s2, evG[qi], 0);
        lp_scatter_kernel<<<MQ, 256, 0, s2>>>(out + ro * V_, rowsum + ro, gts + 2 * ro,
                                              attn_h + ro * T_, zattn + ro, cseq);
    }
    cudaEventRecord(evS0, s2);
    {
        long ro = 3L * MQ;
        lp_scatter_kernel<<<MQ, 256>>>(out + ro * V_, rowsum + ro, gts + 2 * ro,
                                       attn_h + ro * T_, zattn + ro, cseq);
    }
    cudaStreamWaitEvent(0, evS0, 0);
}